// round 1
// baseline (speedup 1.0000x reference)
#include <cuda_runtime.h>
#include <cuda_bf16.h>
#include <math.h>

// ---------------------------------------------------------------------------
// Problem dims (fixed for this dataset)
//   q: (8192, 5, 640) f32   -> MQ = 40960 rows of D=640
//   k,v: (8192, 1, 640) f32 -> MK = 8192 rows
//   W_in: (640, 512), W_out: (512, 640), H=8, DH=64, INNER=512
// ---------------------------------------------------------------------------
#define QLEN   8192
#define NWAY   5
#define DDIM   640
#define INNER  512
#define HEADS  8
#define DH     64
#define MQ     (QLEN * NWAY)   // 40960
#define MK     QLEN            // 8192

// ------------------------- scratch (device globals) ------------------------
__device__ float g_fq[(size_t)MQ * INNER];   // LN(q)@W_in
__device__ float g_fk[(size_t)MK * INNER];   // LN(k)@W_in
__device__ float g_fv[(size_t)MK * INNER];   // LN(v)@W_in
__device__ float g_oin[(size_t)MQ * INNER];  // dots * f_v broadcast
__device__ float g_mu_q[MQ],  g_rs_q[MQ];
__device__ float g_mu_k[MK],  g_rs_k[MK];
__device__ float g_mu_v[MK],  g_rs_v[MK];

// ------------------------- row stats: mean + rstd --------------------------
// one warp per row of 640; block = 8 warps
__global__ __launch_bounds__(256) void row_stats_kernel(
    const float* __restrict__ X, float* __restrict__ mu,
    float* __restrict__ rstd, int rows)
{
    int row  = blockIdx.x * 8 + (threadIdx.x >> 5);
    int lane = threadIdx.x & 31;
    if (row >= rows) return;
    const float* x = X + (size_t)row * DDIM;
    float s = 0.f, s2 = 0.f;
#pragma unroll
    for (int i = 0; i < DDIM / 32; i++) {
        float vv = x[lane + i * 32];
        s += vv; s2 += vv * vv;
    }
#pragma unroll
    for (int o = 16; o > 0; o >>= 1) {
        s  += __shfl_xor_sync(0xffffffffu, s,  o);
        s2 += __shfl_xor_sync(0xffffffffu, s2, o);
    }
    if (lane == 0) {
        float m   = s * (1.f / DDIM);
        float var = s2 * (1.f / DDIM) - m * m;
        mu[row]   = m;
        rstd[row] = rsqrtf(var + 1e-5f);
    }
}

// ------------------------- SGEMM 128x128x8, optional fused LN / bias -------
// C[M,N] = op(X[M,K]) @ W[K,N] (+ bias[N])
// op = LayerNorm along K using per-row mu/rstd and per-col g/b when LN=true.
// Requires M%128==0, N%128==0, K%8==0 (true for all calls here).
template <bool LN, bool BIAS>
__global__ __launch_bounds__(256) void sgemm_ln_kernel(
    const float* __restrict__ X, const float* __restrict__ W,
    const float* __restrict__ mu, const float* __restrict__ rstd,
    const float* __restrict__ lg, const float* __restrict__ lb,
    const float* __restrict__ bias, float* __restrict__ C,
    int M, int N, int K)
{
    __shared__ float As[8][128];
    __shared__ float Bs[8][128];
    const int tid = threadIdx.x;
    const int bm = blockIdx.y * 128;
    const int bn = blockIdx.x * 128;

    const int arow = tid >> 1;            // 0..127
    const int acol = (tid & 1) * 4;       // 0 or 4
    const int brow = tid >> 5;            // 0..7
    const int bcol = (tid & 31) * 4;      // 0..124
    const int tm = (tid >> 4) * 8;        // 0..120
    const int tn = (tid & 15) * 8;        // 0..120

    float acc[8][8];
#pragma unroll
    for (int i = 0; i < 8; i++)
#pragma unroll
        for (int j = 0; j < 8; j++) acc[i][j] = 0.f;

    float rmu = 0.f, rrs = 1.f;
    if (LN) { rmu = mu[bm + arow]; rrs = rstd[bm + arow]; }
    const float* Xrow = X + (size_t)(bm + arow) * K;

    for (int k0 = 0; k0 < K; k0 += 8) {
        float4 av = *reinterpret_cast<const float4*>(Xrow + k0 + acol);
        if (LN) {
            const float4 gv = *reinterpret_cast<const float4*>(lg + k0 + acol);
            const float4 bv = *reinterpret_cast<const float4*>(lb + k0 + acol);
            av.x = (av.x - rmu) * rrs * gv.x + bv.x;
            av.y = (av.y - rmu) * rrs * gv.y + bv.y;
            av.z = (av.z - rmu) * rrs * gv.z + bv.z;
            av.w = (av.w - rmu) * rrs * gv.w + bv.w;
        }
        As[acol + 0][arow] = av.x;
        As[acol + 1][arow] = av.y;
        As[acol + 2][arow] = av.z;
        As[acol + 3][arow] = av.w;
        *reinterpret_cast<float4*>(&Bs[brow][bcol]) =
            *reinterpret_cast<const float4*>(W + (size_t)(k0 + brow) * N + bn + bcol);
        __syncthreads();
#pragma unroll
        for (int kk = 0; kk < 8; kk++) {
            float ra[8], rb[8];
            *reinterpret_cast<float4*>(ra)     = *reinterpret_cast<const float4*>(&As[kk][tm]);
            *reinterpret_cast<float4*>(ra + 4) = *reinterpret_cast<const float4*>(&As[kk][tm + 4]);
            *reinterpret_cast<float4*>(rb)     = *reinterpret_cast<const float4*>(&Bs[kk][tn]);
            *reinterpret_cast<float4*>(rb + 4) = *reinterpret_cast<const float4*>(&Bs[kk][tn + 4]);
#pragma unroll
            for (int i = 0; i < 8; i++)
#pragma unroll
                for (int j = 0; j < 8; j++)
                    acc[i][j] = fmaf(ra[i], rb[j], acc[i][j]);
        }
        __syncthreads();
    }

    float bb[8];
    if (BIAS) {
        *reinterpret_cast<float4*>(bb)     = *reinterpret_cast<const float4*>(bias + bn + tn);
        *reinterpret_cast<float4*>(bb + 4) = *reinterpret_cast<const float4*>(bias + bn + tn + 4);
    }
#pragma unroll
    for (int i = 0; i < 8; i++) {
        float* crow = C + (size_t)(bm + tm + i) * N + bn + tn;
        float4 o0, o1;
        o0.x = acc[i][0] + (BIAS ? bb[0] : 0.f);
        o0.y = acc[i][1] + (BIAS ? bb[1] : 0.f);
        o0.z = acc[i][2] + (BIAS ? bb[2] : 0.f);
        o0.w = acc[i][3] + (BIAS ? bb[3] : 0.f);
        o1.x = acc[i][4] + (BIAS ? bb[4] : 0.f);
        o1.y = acc[i][5] + (BIAS ? bb[5] : 0.f);
        o1.z = acc[i][6] + (BIAS ? bb[6] : 0.f);
        o1.w = acc[i][7] + (BIAS ? bb[7] : 0.f);
        *reinterpret_cast<float4*>(crow)     = o0;
        *reinterpret_cast<float4*>(crow + 4) = o1;
    }
}

// ------------------------- combine: attention weights ----------------------
// One block per q position; warp w = head h. Per head: stats of f_k/f_q over
// DH=64, cosine + variance weights + sigmoid covariance, then
// o_inner[q,n, h*64+d] = c[h,n] * f_v[q, h*64+d].
__global__ __launch_bounds__(256) void combine_kernel(
    const float* __restrict__ fq, const float* __restrict__ fk,
    const float* __restrict__ fv, const float* __restrict__ vs_p,
    const float* __restrict__ cs_p, float* __restrict__ oin)
{
    const int q    = blockIdx.x;
    const int h    = threadIdx.x >> 5;
    const int lane = threadIdx.x & 31;
    const float vscale = *vs_p;
    const float cscale = *cs_p;

    const float* fkp = fk + (size_t)q * INNER + h * DH;
    const float* fvp = fv + (size_t)q * INNER + h * DH;
    const float k0 = fkp[lane], k1 = fkp[lane + 32];
    const float v0 = fvp[lane], v1 = fvp[lane + 32];

    // k stats: mean, uncentered norm, centered variance
    float sk = k0 + k1, sk2 = k0 * k0 + k1 * k1;
#pragma unroll
    for (int o = 16; o > 0; o >>= 1) {
        sk  += __shfl_xor_sync(0xffffffffu, sk,  o);
        sk2 += __shfl_xor_sync(0xffffffffu, sk2, o);
    }
    const float mk = sk * (1.f / DH);
    const float nk = sqrtf(sk2);
    const float ek0 = k0 - mk, ek1 = k1 - mk;
    float skc = ek0 * ek0 + ek1 * ek1;
#pragma unroll
    for (int o = 16; o > 0; o >>= 1)
        skc += __shfl_xor_sync(0xffffffffu, skc, o);
    const float vark = skc * (1.f / DH);

    float base[NWAY], vw[NWAY];
    float vwsum = 0.f;
#pragma unroll
    for (int n = 0; n < NWAY; n++) {
        const float* fqp = fq + ((size_t)q * NWAY + n) * INNER + h * DH;
        const float a0 = fqp[lane], a1 = fqp[lane + 32];
        // pass 1: mean
        float s = a0 + a1;
#pragma unroll
        for (int o = 16; o > 0; o >>= 1)
            s += __shfl_xor_sync(0xffffffffu, s, o);
        const float mq = s * (1.f / DH);
        // pass 2: uncentered norm^2, raw dot, centered variance, centered cov
        const float e0 = a0 - mq, e1 = a1 - mq;
        float s2 = a0 * a0 + a1 * a1;
        float d  = a0 * k0 + a1 * k1;
        float s2c = e0 * e0 + e1 * e1;
        float dc  = e0 * ek0 + e1 * ek1;
#pragma unroll
        for (int o = 16; o > 0; o >>= 1) {
            s2  += __shfl_xor_sync(0xffffffffu, s2,  o);
            d   += __shfl_xor_sync(0xffffffffu, d,   o);
            s2c += __shfl_xor_sync(0xffffffffu, s2c, o);
            dc  += __shfl_xor_sync(0xffffffffu, dc,  o);
        }
        const float nq   = sqrtf(s2);
        const float varq = s2c * (1.f / DH);
        const float cosd = d / (nq * nk);
        const float w    = 1.f / (fabsf(vark - varq) + 1e-6f);
        vw[n]  = w;
        vwsum += w;
        const float cov  = dc * (1.f / (DH + 1e-6f));
        const float sig  = 1.f / (1.f + expf(-cov));
        base[n] = cosd + cscale * sig;
    }
    const float inv = 1.f / (vwsum + 1e-6f);
#pragma unroll
    for (int n = 0; n < NWAY; n++) {
        const float c = base[n] + vscale * vw[n] * inv;
        float* op = oin + ((size_t)q * NWAY + n) * INNER + h * DH;
        op[lane]      = c * v0;
        op[lane + 32] = c * v1;
    }
}

// ---------------------------------------------------------------------------
extern "C" void kernel_launch(void* const* d_in, const int* in_sizes, int n_in,
                              void* d_out, int out_size)
{
    const float* q      = (const float*)d_in[0];
    const float* k      = (const float*)d_in[1];
    const float* v      = (const float*)d_in[2];
    const float* ln_g   = (const float*)d_in[3];
    const float* ln_b   = (const float*)d_in[4];
    const float* W_in   = (const float*)d_in[5];
    const float* W_out  = (const float*)d_in[6];
    const float* b_out  = (const float*)d_in[7];
    const float* vscale = (const float*)d_in[8];
    const float* cscale = (const float*)d_in[9];
    float* out = (float*)d_out;

    float *fq, *fk, *fv, *oin, *muq, *rsq, *muk, *rsk, *muv, *rsv;
    cudaGetSymbolAddress((void**)&fq,  g_fq);
    cudaGetSymbolAddress((void**)&fk,  g_fk);
    cudaGetSymbolAddress((void**)&fv,  g_fv);
    cudaGetSymbolAddress((void**)&oin, g_oin);
    cudaGetSymbolAddress((void**)&muq, g_mu_q);
    cudaGetSymbolAddress((void**)&rsq, g_rs_q);
    cudaGetSymbolAddress((void**)&muk, g_mu_k);
    cudaGetSymbolAddress((void**)&rsk, g_rs_k);
    cudaGetSymbolAddress((void**)&muv, g_mu_v);
    cudaGetSymbolAddress((void**)&rsv, g_rs_v);

    // 1) row stats
    row_stats_kernel<<<MQ / 8, 256>>>(q, muq, rsq, MQ);
    row_stats_kernel<<<MK / 8, 256>>>(k, muk, rsk, MK);
    row_stats_kernel<<<MK / 8, 256>>>(v, muv, rsv, MK);

    // 2) projections: LN(X) @ W_in
    {
        dim3 grid(INNER / 128, MQ / 128);
        sgemm_ln_kernel<true, false><<<grid, 256>>>(
            q, W_in, muq, rsq, ln_g, ln_b, nullptr, fq, MQ, INNER, DDIM);
    }
    {
        dim3 grid(INNER / 128, MK / 128);
        sgemm_ln_kernel<true, false><<<grid, 256>>>(
            k, W_in, muk, rsk, ln_g, ln_b, nullptr, fk, MK, INNER, DDIM);
        sgemm_ln_kernel<true, false><<<grid, 256>>>(
            v, W_in, muv, rsv, ln_g, ln_b, nullptr, fv, MK, INNER, DDIM);
    }

    // 3) attention combine -> o_inner
    combine_kernel<<<QLEN, 256>>>(fq, fk, fv, vscale, cscale, oin);

    // 4) output projection: o_inner @ W_out + b_out
    {
        dim3 grid(DDIM / 128, MQ / 128);
        sgemm_ln_kernel<false, true><<<grid, 256>>>(
            oin, W_out, nullptr, nullptr, nullptr, nullptr, b_out, out,
            MQ, DDIM, INNER);
    }
}

// round 3
// speedup vs baseline: 2.7497x; 2.7497x over previous
#include <cuda_runtime.h>
#include <cuda_bf16.h>
#include <math.h>
#include <stdint.h>

// ---------------------------------------------------------------------------
// dims fixed for this dataset
#define QLEN   8192
#define NWAY   5
#define DDIM   640
#define INNER  512
#define HEADS  8
#define DH     64
#define MQ     (QLEN * NWAY)   // 40960
#define MK     QLEN            // 8192

// ------------------------- scratch (device globals) ------------------------
__device__ __align__(256) float g_fq[(size_t)MQ * INNER];
__device__ __align__(256) float g_fk[(size_t)MK * INNER];
__device__ __align__(256) float g_fv[(size_t)MK * INNER];
__device__ __align__(256) __nv_bfloat16 g_qh[(size_t)MQ * DDIM];
__device__ __align__(256) __nv_bfloat16 g_ql[(size_t)MQ * DDIM];
__device__ __align__(256) __nv_bfloat16 g_kh[(size_t)MK * DDIM];
__device__ __align__(256) __nv_bfloat16 g_kl[(size_t)MK * DDIM];
__device__ __align__(256) __nv_bfloat16 g_vh[(size_t)MK * DDIM];
__device__ __align__(256) __nv_bfloat16 g_vl[(size_t)MK * DDIM];
__device__ __align__(256) __nv_bfloat16 g_oh[(size_t)MQ * INNER];
__device__ __align__(256) __nv_bfloat16 g_ol[(size_t)MQ * INNER];
__device__ __align__(256) __nv_bfloat16 g_wi_h[(size_t)DDIM * INNER];   // K x N
__device__ __align__(256) __nv_bfloat16 g_wi_l[(size_t)DDIM * INNER];
__device__ __align__(256) __nv_bfloat16 g_wo_h[(size_t)INNER * DDIM];   // K x N
__device__ __align__(256) __nv_bfloat16 g_wo_l[(size_t)INNER * DDIM];

// ------------------------- helpers -----------------------------------------
__device__ __forceinline__ uint32_t smem_u32(const void* p) {
    uint32_t a;
    asm("{ .reg .u64 t; cvta.to.shared.u64 t, %1; cvt.u32.u64 %0, t; }"
        : "=r"(a) : "l"(p));
    return a;
}
__device__ __forceinline__ void cp16(uint32_t dst, const void* src) {
    asm volatile(
        "{ .reg .u64 g; cvta.to.global.u64 g, %1;"
        " cp.async.cg.shared.global [%0], [g], 16; }"
        :: "r"(dst), "l"(src) : "memory");
}
__device__ __forceinline__ void cp_commit() {
    asm volatile("cp.async.commit_group;" ::: "memory");
}
__device__ __forceinline__ void cp_wait1() {
    asm volatile("cp.async.wait_group 1;" ::: "memory");
}
__device__ __forceinline__ void cp_wait0() {
    asm volatile("cp.async.wait_group 0;" ::: "memory");
}
__device__ __forceinline__ void ldsm_x4(uint32_t* r, uint32_t addr) {
    asm volatile("ldmatrix.sync.aligned.m8n8.x4.shared.b16 {%0,%1,%2,%3}, [%4];"
                 : "=r"(r[0]), "=r"(r[1]), "=r"(r[2]), "=r"(r[3]) : "r"(addr));
}
__device__ __forceinline__ void ldsm_x4t(uint32_t* r, uint32_t addr) {
    asm volatile("ldmatrix.sync.aligned.m8n8.x4.trans.shared.b16 {%0,%1,%2,%3}, [%4];"
                 : "=r"(r[0]), "=r"(r[1]), "=r"(r[2]), "=r"(r[3]) : "r"(addr));
}
__device__ __forceinline__ void mma16816(float* c, const uint32_t* a,
                                         uint32_t b0, uint32_t b1) {
    asm volatile(
        "mma.sync.aligned.m16n8k16.row.col.f32.bf16.bf16.f32 "
        "{%0,%1,%2,%3}, {%4,%5,%6,%7}, {%8,%9}, {%0,%1,%2,%3};"
        : "+f"(c[0]), "+f"(c[1]), "+f"(c[2]), "+f"(c[3])
        : "r"(a[0]), "r"(a[1]), "r"(a[2]), "r"(a[3]), "r"(b0), "r"(b1));
}

// ------------------------- LN + bf16 split ---------------------------------
__global__ __launch_bounds__(256) void ln_split_kernel(
    const float* __restrict__ X, const float* __restrict__ g,
    const float* __restrict__ b, __nv_bfloat16* __restrict__ Xh,
    __nv_bfloat16* __restrict__ Xl, int rows)
{
    int row  = blockIdx.x * 8 + (threadIdx.x >> 5);
    int lane = threadIdx.x & 31;
    if (row >= rows) return;
    const float* x = X + (size_t)row * DDIM;
    float v[20];
    float s = 0.f, s2 = 0.f;
#pragma unroll
    for (int i = 0; i < 20; i++) {
        v[i] = x[lane + i * 32];
        s += v[i]; s2 += v[i] * v[i];
    }
#pragma unroll
    for (int o = 16; o > 0; o >>= 1) {
        s  += __shfl_xor_sync(0xffffffffu, s,  o);
        s2 += __shfl_xor_sync(0xffffffffu, s2, o);
    }
    float m   = s * (1.f / DDIM);
    float var = s2 * (1.f / DDIM) - m * m;
    float rs  = rsqrtf(var + 1e-5f);
#pragma unroll
    for (int i = 0; i < 20; i++) {
        int c = lane + i * 32;
        float xn = (v[i] - m) * rs * g[c] + b[c];
        __nv_bfloat16 h = __float2bfloat16(xn);
        Xh[(size_t)row * DDIM + c] = h;
        Xl[(size_t)row * DDIM + c] = __float2bfloat16(xn - __bfloat162float(h));
    }
}

// ------------------------- W split (elementwise, layout kept K x N) ---------
__global__ __launch_bounds__(256) void wsplit_kernel(
    const float* __restrict__ W, __nv_bfloat16* __restrict__ Th,
    __nv_bfloat16* __restrict__ Tl, int total)
{
    int idx = blockIdx.x * 256 + threadIdx.x;
    if (idx >= total) return;
    float w = W[idx];
    __nv_bfloat16 h = __float2bfloat16(w);
    Th[idx] = h;
    Tl[idx] = __float2bfloat16(w - __bfloat162float(h));
}

// ------------------------- bf16x2-split GEMM via mma.sync -------------------
// C[M, Ntot] = (Ah+Al)[M, KD] @ (Bh+Bl)[KD, Ntot] (+bias), fp32 accum.
// CTA tile 128x128, BK=64, double-buffered cp.async. 8 warps (2m x 4n),
// warp tile 64x32. A smem: [128][64] bf16 (128B rows, ^((m&7)<<4)).
// B smem: [64][128] bf16 (256B rows, ^((k&7)<<4)).
#define ASZ 16384
#define STG 65536
template <int KD, bool BIAS>
__global__ __launch_bounds__(256, 1) void gemm_mma(
    const __nv_bfloat16* __restrict__ Ah, const __nv_bfloat16* __restrict__ Al,
    const __nv_bfloat16* __restrict__ Bh, const __nv_bfloat16* __restrict__ Bl,
    const float* __restrict__ bias, float* __restrict__ C, int Ntot)
{
    constexpr int NC = KD / 64;
    extern __shared__ char smraw[];
    const uint32_t sb = (smem_u32(smraw) + 127u) & ~127u;

    const int tid  = threadIdx.x;
    const int wid  = tid >> 5;
    const int lane = tid & 31;
    const int bm   = blockIdx.y * 128;
    const int bn   = blockIdx.x * 128;
    const int wm   = (wid >> 2) * 64;   // 0 or 64
    const int wn   = (wid & 3) * 32;    // 0..96

    float acc[4][4][4];
#pragma unroll
    for (int i = 0; i < 4; i++)
#pragma unroll
        for (int j = 0; j < 4; j++)
#pragma unroll
            for (int t = 0; t < 4; t++) acc[i][j][t] = 0.f;

    // ---- stage loader ----
    auto load_stage = [&](int s, int c) {
        const uint32_t base = sb + (uint32_t)s * STG;
        const int kb = c * 64;
#pragma unroll
        for (int u = tid; u < 1024; u += 256) {
            int r = u >> 3, kc = u & 7;
            uint32_t off = (uint32_t)(r * 128 + kc * 16) ^ (uint32_t)((r & 7) << 4);
            const size_t gi = (size_t)(bm + r) * KD + kb + kc * 8;
            cp16(base + off,       Ah + gi);
            cp16(base + ASZ + off, Al + gi);
        }
#pragma unroll
        for (int u = tid; u < 1024; u += 256) {
            int kk = u >> 4, nc2 = u & 15;
            uint32_t off = (uint32_t)(kk * 256 + nc2 * 16) ^ (uint32_t)((kk & 7) << 4);
            const size_t gi = (size_t)(kb + kk) * Ntot + bn + nc2 * 8;
            cp16(base + 2 * ASZ + off, Bh + gi);
            cp16(base + 3 * ASZ + off, Bl + gi);
        }
        cp_commit();
    };

    load_stage(0, 0);

    // per-lane fragment address components
    const int arow = wm + (lane & 15);            // A ldmatrix row within tile
    const int acol16 = (lane >> 4) * 16;          // 0 or 16 bytes
    const int brow0 = ((lane >> 3) & 1) * 8 + (lane & 7);  // k within 16-step
    const int bnc   = wn + (lane >> 4) * 8;       // n col for this lane's matrix

    for (int c = 0; c < NC; c++) {
        if (c + 1 < NC) { load_stage((c + 1) & 1, c + 1); cp_wait1(); }
        else           { cp_wait0(); }
        __syncthreads();

        const uint32_t base = sb + (uint32_t)(c & 1) * STG;
#pragma unroll
        for (int ks = 0; ks < 4; ks++) {
            uint32_t ahf[4][4], alf[4][4], bhf[8], blf[8];
#pragma unroll
            for (int mf = 0; mf < 4; mf++) {
                int r = arow + mf * 16;
                uint32_t off = (uint32_t)(r * 128 + ks * 32 + acol16)
                             ^ (uint32_t)((r & 7) << 4);
                ldsm_x4(ahf[mf], base + off);
                ldsm_x4(alf[mf], base + ASZ + off);
            }
#pragma unroll
            for (int g2 = 0; g2 < 2; g2++) {
                int kk = ks * 16 + brow0;
                int nn = bnc + g2 * 16;
                uint32_t off = (uint32_t)(kk * 256 + nn * 2)
                             ^ (uint32_t)((kk & 7) << 4);
                ldsm_x4t(&bhf[g2 * 4], base + 2 * ASZ + off);
                ldsm_x4t(&blf[g2 * 4], base + 3 * ASZ + off);
            }
#pragma unroll
            for (int mf = 0; mf < 4; mf++)
#pragma unroll
                for (int nf = 0; nf < 4; nf++) {
                    mma16816(acc[mf][nf], ahf[mf], bhf[nf * 2], bhf[nf * 2 + 1]);
                    mma16816(acc[mf][nf], ahf[mf], blf[nf * 2], blf[nf * 2 + 1]);
                    mma16816(acc[mf][nf], alf[mf], bhf[nf * 2], bhf[nf * 2 + 1]);
                }
        }
        __syncthreads();
    }

    // ---- epilogue ----
    const int r0 = bm + wm + (lane >> 2);
    const int c0 = bn + wn + (lane & 3) * 2;
#pragma unroll
    for (int mf = 0; mf < 4; mf++) {
#pragma unroll
        for (int nf = 0; nf < 4; nf++) {
            int gr0 = r0 + mf * 16;
            int gc  = c0 + nf * 8;
            float b0 = 0.f, b1 = 0.f;
            if (BIAS) { b0 = bias[gc]; b1 = bias[gc + 1]; }
            float2 v0 = make_float2(acc[mf][nf][0] + b0, acc[mf][nf][1] + b1);
            float2 v1 = make_float2(acc[mf][nf][2] + b0, acc[mf][nf][3] + b1);
            *reinterpret_cast<float2*>(C + (size_t)gr0 * Ntot + gc)       = v0;
            *reinterpret_cast<float2*>(C + (size_t)(gr0 + 8) * Ntot + gc) = v1;
        }
    }
}

// ------------------------- combine: attention weights ----------------------
__global__ __launch_bounds__(256) void combine_kernel(
    const float* __restrict__ fq, const float* __restrict__ fk,
    const float* __restrict__ fv, const float* __restrict__ vs_p,
    const float* __restrict__ cs_p, __nv_bfloat16* __restrict__ oh,
    __nv_bfloat16* __restrict__ ol)
{
    const int q    = blockIdx.x;
    const int h    = threadIdx.x >> 5;
    const int lane = threadIdx.x & 31;
    const float vscale = *vs_p;
    const float cscale = *cs_p;

    const float* fkp = fk + (size_t)q * INNER + h * DH;
    const float* fvp = fv + (size_t)q * INNER + h * DH;
    const float k0 = fkp[lane], k1 = fkp[lane + 32];
    const float v0 = fvp[lane], v1 = fvp[lane + 32];

    float sk = k0 + k1, sk2 = k0 * k0 + k1 * k1;
#pragma unroll
    for (int o = 16; o > 0; o >>= 1) {
        sk  += __shfl_xor_sync(0xffffffffu, sk,  o);
        sk2 += __shfl_xor_sync(0xffffffffu, sk2, o);
    }
    const float mk = sk * (1.f / DH);
    const float nk = sqrtf(sk2);
    const float ek0 = k0 - mk, ek1 = k1 - mk;
    float skc = ek0 * ek0 + ek1 * ek1;
#pragma unroll
    for (int o = 16; o > 0; o >>= 1)
        skc += __shfl_xor_sync(0xffffffffu, skc, o);
    const float vark = skc * (1.f / DH);

    float base[NWAY], vw[NWAY];
    float vwsum = 0.f;
#pragma unroll
    for (int n = 0; n < NWAY; n++) {
        const float* fqp = fq + ((size_t)q * NWAY + n) * INNER + h * DH;
        const float a0 = fqp[lane], a1 = fqp[lane + 32];
        float s = a0 + a1;
#pragma unroll
        for (int o = 16; o > 0; o >>= 1)
            s += __shfl_xor_sync(0xffffffffu, s, o);
        const float mq = s * (1.f / DH);
        const float e0 = a0 - mq, e1 = a1 - mq;
        float s2 = a0 * a0 + a1 * a1;
        float d  = a0 * k0 + a1 * k1;
        float s2c = e0 * e0 + e1 * e1;
        float dc  = e0 * ek0 + e1 * ek1;
#pragma unroll
        for (int o = 16; o > 0; o >>= 1) {
            s2  += __shfl_xor_sync(0xffffffffu, s2,  o);
            d   += __shfl_xor_sync(0xffffffffu, d,   o);
            s2c += __shfl_xor_sync(0xffffffffu, s2c, o);
            dc  += __shfl_xor_sync(0xffffffffu, dc,  o);
        }
        const float nq   = sqrtf(s2);
        const float varq = s2c * (1.f / DH);
        const float cosd = d / (nq * nk);
        const float w    = 1.f / (fabsf(vark - varq) + 1e-6f);
        vw[n]  = w;
        vwsum += w;
        const float cov  = dc * (1.f / (DH + 1e-6f));
        const float sig  = 1.f / (1.f + expf(-cov));
        base[n] = cosd + cscale * sig;
    }
    const float inv = 1.f / (vwsum + 1e-6f);
#pragma unroll
    for (int n = 0; n < NWAY; n++) {
        const float c = base[n] + vscale * vw[n] * inv;
        const size_t o0 = ((size_t)q * NWAY + n) * INNER + h * DH;
        float x0 = c * v0, x1 = c * v1;
        __nv_bfloat16 h0 = __float2bfloat16(x0);
        __nv_bfloat16 h1 = __float2bfloat16(x1);
        oh[o0 + lane]      = h0;
        oh[o0 + lane + 32] = h1;
        ol[o0 + lane]      = __float2bfloat16(x0 - __bfloat162float(h0));
        ol[o0 + lane + 32] = __float2bfloat16(x1 - __bfloat162float(h1));
    }
}

// ---------------------------------------------------------------------------
extern "C" void kernel_launch(void* const* d_in, const int* in_sizes, int n_in,
                              void* d_out, int out_size)
{
    const float* q      = (const float*)d_in[0];
    const float* k      = (const float*)d_in[1];
    const float* v      = (const float*)d_in[2];
    const float* ln_g   = (const float*)d_in[3];
    const float* ln_b   = (const float*)d_in[4];
    const float* W_in   = (const float*)d_in[5];
    const float* W_out  = (const float*)d_in[6];
    const float* b_out  = (const float*)d_in[7];
    const float* vscale = (const float*)d_in[8];
    const float* cscale = (const float*)d_in[9];
    float* out = (float*)d_out;

    float *fq, *fk, *fv;
    __nv_bfloat16 *qh, *ql, *kh, *kl, *vh, *vl, *oh, *ol, *wih, *wil, *woh, *wol;
    cudaGetSymbolAddress((void**)&fq, g_fq);
    cudaGetSymbolAddress((void**)&fk, g_fk);
    cudaGetSymbolAddress((void**)&fv, g_fv);
    cudaGetSymbolAddress((void**)&qh, g_qh);
    cudaGetSymbolAddress((void**)&ql, g_ql);
    cudaGetSymbolAddress((void**)&kh, g_kh);
    cudaGetSymbolAddress((void**)&kl, g_kl);
    cudaGetSymbolAddress((void**)&vh, g_vh);
    cudaGetSymbolAddress((void**)&vl, g_vl);
    cudaGetSymbolAddress((void**)&oh, g_oh);
    cudaGetSymbolAddress((void**)&ol, g_ol);
    cudaGetSymbolAddress((void**)&wih, g_wi_h);
    cudaGetSymbolAddress((void**)&wil, g_wi_l);
    cudaGetSymbolAddress((void**)&woh, g_wo_h);
    cudaGetSymbolAddress((void**)&wol, g_wo_l);

    const int SMEM = 2 * STG + 128;  // 128KB + align pad
    static int attr_done = 0;
    cudaFuncSetAttribute(gemm_mma<640, false>,
                         cudaFuncAttributeMaxDynamicSharedMemorySize, SMEM);
    cudaFuncSetAttribute(gemm_mma<512, true>,
                         cudaFuncAttributeMaxDynamicSharedMemorySize, SMEM);
    (void)attr_done;

    // 1) LN + split
    ln_split_kernel<<<MQ / 8, 256>>>(q, ln_g, ln_b, qh, ql, MQ);
    ln_split_kernel<<<MK / 8, 256>>>(k, ln_g, ln_b, kh, kl, MK);
    ln_split_kernel<<<MK / 8, 256>>>(v, ln_g, ln_b, vh, vl, MK);

    // 2) weight split (layout already K x N)
    wsplit_kernel<<<(DDIM * INNER + 255) / 256, 256>>>(W_in,  wih, wil, DDIM * INNER);
    wsplit_kernel<<<(INNER * DDIM + 255) / 256, 256>>>(W_out, woh, wol, INNER * DDIM);

    // 3) projections on tensor cores (mma.sync bf16 split)
    gemm_mma<640, false><<<dim3(INNER / 128, MQ / 128), 256, SMEM>>>(
        qh, ql, wih, wil, nullptr, fq, INNER);
    gemm_mma<640, false><<<dim3(INNER / 128, MK / 128), 256, SMEM>>>(
        kh, kl, wih, wil, nullptr, fk, INNER);
    gemm_mma<640, false><<<dim3(INNER / 128, MK / 128), 256, SMEM>>>(
        vh, vl, wih, wil, nullptr, fv, INNER);

    // 4) attention combine -> split o_inner
    combine_kernel<<<QLEN, 256>>>(fq, fk, fv, vscale, cscale, oh, ol);

    // 5) output projection + bias
    gemm_mma<512, true><<<dim3(DDIM / 128, MQ / 128), 256, SMEM>>>(
        oh, ol, woh, wol, b_out, out, DDIM);
}

// round 4
// speedup vs baseline: 3.4684x; 1.2614x over previous
#include <cuda_runtime.h>
#include <cuda_bf16.h>
#include <cuda_fp16.h>
#include <math.h>
#include <stdint.h>

// ---------------------------------------------------------------------------
// dims fixed for this dataset
#define QLEN   8192
#define NWAY   5
#define DDIM   640
#define INNER  512
#define HEADS  8
#define DH     64
#define MQ     (QLEN * NWAY)   // 40960
#define MK     QLEN            // 8192

// ------------------------- scratch (device globals) ------------------------
__device__ __align__(256) float g_fq[(size_t)MQ * INNER];
__device__ __align__(256) float g_fk[(size_t)MK * INNER];
__device__ __align__(256) float g_fv[(size_t)MK * INNER];
__device__ __align__(256) __nv_bfloat16 g_qh[(size_t)MQ * DDIM];
__device__ __align__(256) __nv_bfloat16 g_ql[(size_t)MQ * DDIM];
__device__ __align__(256) __nv_bfloat16 g_kh[(size_t)MK * DDIM];
__device__ __align__(256) __nv_bfloat16 g_kl[(size_t)MK * DDIM];
__device__ __align__(256) __nv_bfloat16 g_vh[(size_t)MK * DDIM];
__device__ __align__(256) __nv_bfloat16 g_vl[(size_t)MK * DDIM];
__device__ __align__(256) __half        g_o [(size_t)MQ * INNER];   // fp16 o_inner
__device__ __align__(256) __nv_bfloat16 g_wi_h[(size_t)DDIM * INNER];   // K x N
__device__ __align__(256) __nv_bfloat16 g_wi_l[(size_t)DDIM * INNER];
__device__ __align__(256) __half        g_wo_f[(size_t)INNER * DDIM];   // K x N fp16

// ------------------------- helpers -----------------------------------------
__device__ __forceinline__ uint32_t smem_u32(const void* p) {
    uint32_t a;
    asm("{ .reg .u64 t; cvta.to.shared.u64 t, %1; cvt.u32.u64 %0, t; }"
        : "=r"(a) : "l"(p));
    return a;
}
__device__ __forceinline__ void cp16(uint32_t dst, const void* src) {
    asm volatile(
        "{ .reg .u64 g; cvta.to.global.u64 g, %1;"
        " cp.async.cg.shared.global [%0], [g], 16; }"
        :: "r"(dst), "l"(src) : "memory");
}
__device__ __forceinline__ void cp_commit() {
    asm volatile("cp.async.commit_group;" ::: "memory");
}
__device__ __forceinline__ void cp_wait0() {
    asm volatile("cp.async.wait_group 0;" ::: "memory");
}
__device__ __forceinline__ void cp_wait1() {
    asm volatile("cp.async.wait_group 1;" ::: "memory");
}
__device__ __forceinline__ void cp_wait2() {
    asm volatile("cp.async.wait_group 2;" ::: "memory");
}
__device__ __forceinline__ void ldsm_x4(uint32_t* r, uint32_t addr) {
    asm volatile("ldmatrix.sync.aligned.m8n8.x4.shared.b16 {%0,%1,%2,%3}, [%4];"
                 : "=r"(r[0]), "=r"(r[1]), "=r"(r[2]), "=r"(r[3]) : "r"(addr));
}
__device__ __forceinline__ void ldsm_x4t(uint32_t* r, uint32_t addr) {
    asm volatile("ldmatrix.sync.aligned.m8n8.x4.trans.shared.b16 {%0,%1,%2,%3}, [%4];"
                 : "=r"(r[0]), "=r"(r[1]), "=r"(r[2]), "=r"(r[3]) : "r"(addr));
}
__device__ __forceinline__ void mma_bf16(float* c, const uint32_t* a,
                                         uint32_t b0, uint32_t b1) {
    asm volatile(
        "mma.sync.aligned.m16n8k16.row.col.f32.bf16.bf16.f32 "
        "{%0,%1,%2,%3}, {%4,%5,%6,%7}, {%8,%9}, {%0,%1,%2,%3};"
        : "+f"(c[0]), "+f"(c[1]), "+f"(c[2]), "+f"(c[3])
        : "r"(a[0]), "r"(a[1]), "r"(a[2]), "r"(a[3]), "r"(b0), "r"(b1));
}
__device__ __forceinline__ void mma_fp16(float* c, const uint32_t* a,
                                         uint32_t b0, uint32_t b1) {
    asm volatile(
        "mma.sync.aligned.m16n8k16.row.col.f32.f16.f16.f32 "
        "{%0,%1,%2,%3}, {%4,%5,%6,%7}, {%8,%9}, {%0,%1,%2,%3};"
        : "+f"(c[0]), "+f"(c[1]), "+f"(c[2]), "+f"(c[3])
        : "r"(a[0]), "r"(a[1]), "r"(a[2]), "r"(a[3]), "r"(b0), "r"(b1));
}

// ------------------------- LN + bf16 split ---------------------------------
__global__ __launch_bounds__(256) void ln_split_kernel(
    const float* __restrict__ X, const float* __restrict__ g,
    const float* __restrict__ b, __nv_bfloat16* __restrict__ Xh,
    __nv_bfloat16* __restrict__ Xl, int rows)
{
    int row  = blockIdx.x * 8 + (threadIdx.x >> 5);
    int lane = threadIdx.x & 31;
    if (row >= rows) return;
    const float* x = X + (size_t)row * DDIM;
    float v[20];
    float s = 0.f, s2 = 0.f;
#pragma unroll
    for (int i = 0; i < 20; i++) {
        v[i] = x[lane + i * 32];
        s += v[i]; s2 += v[i] * v[i];
    }
#pragma unroll
    for (int o = 16; o > 0; o >>= 1) {
        s  += __shfl_xor_sync(0xffffffffu, s,  o);
        s2 += __shfl_xor_sync(0xffffffffu, s2, o);
    }
    float m   = s * (1.f / DDIM);
    float var = s2 * (1.f / DDIM) - m * m;
    float rs  = rsqrtf(var + 1e-5f);
#pragma unroll
    for (int i = 0; i < 20; i++) {
        int c = lane + i * 32;
        float xn = (v[i] - m) * rs * g[c] + b[c];
        __nv_bfloat16 h = __float2bfloat16(xn);
        Xh[(size_t)row * DDIM + c] = h;
        Xl[(size_t)row * DDIM + c] = __float2bfloat16(xn - __bfloat162float(h));
    }
}

// ------------------------- W splits ----------------------------------------
__global__ __launch_bounds__(256) void wsplit_kernel(
    const float* __restrict__ W, __nv_bfloat16* __restrict__ Th,
    __nv_bfloat16* __restrict__ Tl, int total)
{
    int idx = blockIdx.x * 256 + threadIdx.x;
    if (idx >= total) return;
    float w = W[idx];
    __nv_bfloat16 h = __float2bfloat16(w);
    Th[idx] = h;
    Tl[idx] = __float2bfloat16(w - __bfloat162float(h));
}
__global__ __launch_bounds__(256) void whalf_kernel(
    const float* __restrict__ W, __half* __restrict__ T, int total)
{
    int idx = blockIdx.x * 256 + threadIdx.x;
    if (idx >= total) return;
    T[idx] = __float2half(W[idx]);
}

// ------------------------- GEMM via mma.sync --------------------------------
// SPLIT3=true : C = (Ah+Al) @ (Bh+Bl) 3-pass bf16 (drops AlBl), fp32 accum.
// SPLIT3=false: C = Ah @ Bh single-pass fp16.
// CTA tile 128x128, BK=64, 3-stage cp.async. 8 warps (2m x 4n), warp 64x32.
// A smem [128][64] (128B rows, ^((m&7)<<4)); B smem [64][128] (256B rows,
// ^((k&7)<<4)).
#define ASZ 16384
template <int KD, bool BIAS, bool SPLIT3>
__global__ __launch_bounds__(256, SPLIT3 ? 1 : 2) void gemm_mma(
    const void* __restrict__ Ah_, const void* __restrict__ Al_,
    const void* __restrict__ Bh_, const void* __restrict__ Bl_,
    const float* __restrict__ bias, float* __restrict__ C, int Ntot)
{
    constexpr int NC   = KD / 64;
    constexpr int STG  = SPLIT3 ? 65536 : 32768;
    constexpr int BOFF = SPLIT3 ? 32768 : 16384;
    const uint16_t* Ah = (const uint16_t*)Ah_;
    const uint16_t* Al = (const uint16_t*)Al_;
    const uint16_t* Bh = (const uint16_t*)Bh_;
    const uint16_t* Bl = (const uint16_t*)Bl_;

    extern __shared__ char smraw[];
    const uint32_t sb = (smem_u32(smraw) + 127u) & ~127u;

    const int tid  = threadIdx.x;
    const int lane = tid & 31;
    const int wid  = tid >> 5;
    const int bm   = blockIdx.y * 128;
    const int bn   = blockIdx.x * 128;
    const int wm   = (wid >> 2) * 64;
    const int wn   = (wid & 3) * 32;

    float acc[4][4][4];
#pragma unroll
    for (int i = 0; i < 4; i++)
#pragma unroll
        for (int j = 0; j < 4; j++)
#pragma unroll
            for (int t = 0; t < 4; t++) acc[i][j][t] = 0.f;

    auto load_stage = [&](int s, int c) {
        const uint32_t base = sb + (uint32_t)s * STG;
        const int kb = c * 64;
#pragma unroll
        for (int u = tid; u < 1024; u += 256) {
            int r = u >> 3, kc = u & 7;
            uint32_t off = (uint32_t)(r * 128 + kc * 16) ^ (uint32_t)((r & 7) << 4);
            const size_t gi = (size_t)(bm + r) * KD + kb + kc * 8;
            cp16(base + off, Ah + gi);
            if (SPLIT3) cp16(base + ASZ + off, Al + gi);
        }
#pragma unroll
        for (int u = tid; u < 1024; u += 256) {
            int kk = u >> 4, nc2 = u & 15;
            uint32_t off = (uint32_t)(kk * 256 + nc2 * 16) ^ (uint32_t)((kk & 7) << 4);
            const size_t gi = (size_t)(kb + kk) * Ntot + bn + nc2 * 8;
            cp16(base + BOFF + off, Bh + gi);
            if (SPLIT3) cp16(base + BOFF + ASZ + off, Bl + gi);
        }
        cp_commit();
    };

    load_stage(0, 0);
    if (NC > 1) load_stage(1, 1);

    const int arow   = wm + (lane & 15);
    const int acol16 = (lane >> 4) * 16;
    const int brow0  = ((lane >> 3) & 1) * 8 + (lane & 7);
    const int bnc    = wn + (lane >> 4) * 8;

    int sidx = 0;
    for (int c = 0; c < NC; c++) {
        if (c + 2 < NC) {
            int ns = sidx + 2; if (ns >= 3) ns -= 3;
            load_stage(ns, c + 2);
            cp_wait2();
        } else if (c + 1 < NC) {
            cp_wait1();
        } else {
            cp_wait0();
        }
        __syncthreads();

        const uint32_t base = sb + (uint32_t)sidx * STG;
#pragma unroll
        for (int ks = 0; ks < 4; ks++) {
            uint32_t ahf[4][4], bhf[8];
#pragma unroll
            for (int mf = 0; mf < 4; mf++) {
                int r = arow + mf * 16;
                uint32_t off = (uint32_t)(r * 128 + ks * 32 + acol16)
                             ^ (uint32_t)((r & 7) << 4);
                ldsm_x4(ahf[mf], base + off);
            }
#pragma unroll
            for (int g2 = 0; g2 < 2; g2++) {
                int kk = ks * 16 + brow0;
                int nn = bnc + g2 * 16;
                uint32_t off = (uint32_t)(kk * 256 + nn * 2)
                             ^ (uint32_t)((kk & 7) << 4);
                ldsm_x4t(&bhf[g2 * 4], base + BOFF + off);
            }
            if (SPLIT3) {
                uint32_t alf[4][4], blf[8];
#pragma unroll
                for (int mf = 0; mf < 4; mf++) {
                    int r = arow + mf * 16;
                    uint32_t off = (uint32_t)(r * 128 + ks * 32 + acol16)
                                 ^ (uint32_t)((r & 7) << 4);
                    ldsm_x4(alf[mf], base + ASZ + off);
                }
#pragma unroll
                for (int g2 = 0; g2 < 2; g2++) {
                    int kk = ks * 16 + brow0;
                    int nn = bnc + g2 * 16;
                    uint32_t off = (uint32_t)(kk * 256 + nn * 2)
                                 ^ (uint32_t)((kk & 7) << 4);
                    ldsm_x4t(&blf[g2 * 4], base + BOFF + ASZ + off);
                }
#pragma unroll
                for (int mf = 0; mf < 4; mf++)
#pragma unroll
                    for (int nf = 0; nf < 4; nf++) {
                        mma_bf16(acc[mf][nf], ahf[mf], bhf[nf * 2], bhf[nf * 2 + 1]);
                        mma_bf16(acc[mf][nf], ahf[mf], blf[nf * 2], blf[nf * 2 + 1]);
                        mma_bf16(acc[mf][nf], alf[mf], bhf[nf * 2], bhf[nf * 2 + 1]);
                    }
            } else {
#pragma unroll
                for (int mf = 0; mf < 4; mf++)
#pragma unroll
                    for (int nf = 0; nf < 4; nf++)
                        mma_fp16(acc[mf][nf], ahf[mf], bhf[nf * 2], bhf[nf * 2 + 1]);
            }
        }
        __syncthreads();
        sidx++; if (sidx == 3) sidx = 0;
    }

    // ---- epilogue ----
    const int r0 = bm + wm + (lane >> 2);
    const int c0 = bn + wn + (lane & 3) * 2;
#pragma unroll
    for (int mf = 0; mf < 4; mf++) {
#pragma unroll
        for (int nf = 0; nf < 4; nf++) {
            int gr0 = r0 + mf * 16;
            int gc  = c0 + nf * 8;
            float b0 = 0.f, b1 = 0.f;
            if (BIAS) { b0 = bias[gc]; b1 = bias[gc + 1]; }
            float2 v0 = make_float2(acc[mf][nf][0] + b0, acc[mf][nf][1] + b1);
            float2 v1 = make_float2(acc[mf][nf][2] + b0, acc[mf][nf][3] + b1);
            *reinterpret_cast<float2*>(C + (size_t)gr0 * Ntot + gc)       = v0;
            *reinterpret_cast<float2*>(C + (size_t)(gr0 + 8) * Ntot + gc) = v1;
        }
    }
}

// ------------------------- combine: attention weights ----------------------
__global__ __launch_bounds__(256) void combine_kernel(
    const float* __restrict__ fq, const float* __restrict__ fk,
    const float* __restrict__ fv, const float* __restrict__ vs_p,
    const float* __restrict__ cs_p, __half* __restrict__ oo)
{
    const int q    = blockIdx.x;
    const int h    = threadIdx.x >> 5;
    const int lane = threadIdx.x & 31;
    const float vscale = *vs_p;
    const float cscale = *cs_p;

    const float* fkp = fk + (size_t)q * INNER + h * DH;
    const float* fvp = fv + (size_t)q * INNER + h * DH;
    const float k0 = fkp[lane], k1 = fkp[lane + 32];
    const float v0 = fvp[lane], v1 = fvp[lane + 32];

    float sk = k0 + k1, sk2 = k0 * k0 + k1 * k1;
#pragma unroll
    for (int o = 16; o > 0; o >>= 1) {
        sk  += __shfl_xor_sync(0xffffffffu, sk,  o);
        sk2 += __shfl_xor_sync(0xffffffffu, sk2, o);
    }
    const float mk = sk * (1.f / DH);
    const float nk = sqrtf(sk2);
    const float ek0 = k0 - mk, ek1 = k1 - mk;
    float skc = ek0 * ek0 + ek1 * ek1;
#pragma unroll
    for (int o = 16; o > 0; o >>= 1)
        skc += __shfl_xor_sync(0xffffffffu, skc, o);
    const float vark = skc * (1.f / DH);

    float base[NWAY], vw[NWAY];
    float vwsum = 0.f;
#pragma unroll
    for (int n = 0; n < NWAY; n++) {
        const float* fqp = fq + ((size_t)q * NWAY + n) * INNER + h * DH;
        const float a0 = fqp[lane], a1 = fqp[lane + 32];
        float s = a0 + a1;
#pragma unroll
        for (int o = 16; o > 0; o >>= 1)
            s += __shfl_xor_sync(0xffffffffu, s, o);
        const float mq = s * (1.f / DH);
        const float e0 = a0 - mq, e1 = a1 - mq;
        float s2 = a0 * a0 + a1 * a1;
        float d  = a0 * k0 + a1 * k1;
        float s2c = e0 * e0 + e1 * e1;
        float dc  = e0 * ek0 + e1 * ek1;
#pragma unroll
        for (int o = 16; o > 0; o >>= 1) {
            s2  += __shfl_xor_sync(0xffffffffu, s2,  o);
            d   += __shfl_xor_sync(0xffffffffu, d,   o);
            s2c += __shfl_xor_sync(0xffffffffu, s2c, o);
            dc  += __shfl_xor_sync(0xffffffffu, dc,  o);
        }
        const float nq   = sqrtf(s2);
        const float varq = s2c * (1.f / DH);
        const float cosd = d / (nq * nk);
        const float w    = 1.f / (fabsf(vark - varq) + 1e-6f);
        vw[n]  = w;
        vwsum += w;
        const float cov  = dc * (1.f / (DH + 1e-6f));
        const float sig  = 1.f / (1.f + expf(-cov));
        base[n] = cosd + cscale * sig;
    }
    const float inv = 1.f / (vwsum + 1e-6f);
#pragma unroll
    for (int n = 0; n < NWAY; n++) {
        const float c = base[n] + vscale * vw[n] * inv;
        const size_t o0 = ((size_t)q * NWAY + n) * INNER + h * DH;
        oo[o0 + lane]      = __float2half(c * v0);
        oo[o0 + lane + 32] = __float2half(c * v1);
    }
}

// ---------------------------------------------------------------------------
extern "C" void kernel_launch(void* const* d_in, const int* in_sizes, int n_in,
                              void* d_out, int out_size)
{
    const float* q      = (const float*)d_in[0];
    const float* k      = (const float*)d_in[1];
    const float* v      = (const float*)d_in[2];
    const float* ln_g   = (const float*)d_in[3];
    const float* ln_b   = (const float*)d_in[4];
    const float* W_in   = (const float*)d_in[5];
    const float* W_out  = (const float*)d_in[6];
    const float* b_out  = (const float*)d_in[7];
    const float* vscale = (const float*)d_in[8];
    const float* cscale = (const float*)d_in[9];
    float* out = (float*)d_out;

    float *fq, *fk, *fv;
    __nv_bfloat16 *qh, *ql, *kh, *kl, *vh, *vl, *wih, *wil;
    __half *oo, *wof;
    cudaGetSymbolAddress((void**)&fq, g_fq);
    cudaGetSymbolAddress((void**)&fk, g_fk);
    cudaGetSymbolAddress((void**)&fv, g_fv);
    cudaGetSymbolAddress((void**)&qh, g_qh);
    cudaGetSymbolAddress((void**)&ql, g_ql);
    cudaGetSymbolAddress((void**)&kh, g_kh);
    cudaGetSymbolAddress((void**)&kl, g_kl);
    cudaGetSymbolAddress((void**)&vh, g_vh);
    cudaGetSymbolAddress((void**)&vl, g_vl);
    cudaGetSymbolAddress((void**)&oo, g_o);
    cudaGetSymbolAddress((void**)&wih, g_wi_h);
    cudaGetSymbolAddress((void**)&wil, g_wi_l);
    cudaGetSymbolAddress((void**)&wof, g_wo_f);

    const int SMEM3 = 3 * 65536 + 128;  // 3-stage, split3
    const int SMEM1 = 3 * 32768 + 128;  // 3-stage, single-pass
    cudaFuncSetAttribute(gemm_mma<640, false, true>,
                         cudaFuncAttributeMaxDynamicSharedMemorySize, SMEM3);
    cudaFuncSetAttribute(gemm_mma<512, true, false>,
                         cudaFuncAttributeMaxDynamicSharedMemorySize, SMEM1);

    // 1) LN + split
    ln_split_kernel<<<MQ / 8, 256>>>(q, ln_g, ln_b, qh, ql, MQ);
    ln_split_kernel<<<MK / 8, 256>>>(k, ln_g, ln_b, kh, kl, MK);
    ln_split_kernel<<<MK / 8, 256>>>(v, ln_g, ln_b, vh, vl, MK);

    // 2) weight prep
    wsplit_kernel<<<(DDIM * INNER + 255) / 256, 256>>>(W_in, wih, wil, DDIM * INNER);
    whalf_kernel<<<(INNER * DDIM + 255) / 256, 256>>>(W_out, wof, INNER * DDIM);

    // 3) projections: 3-pass bf16-split on tensor cores
    gemm_mma<640, false, true><<<dim3(INNER / 128, MQ / 128), 256, SMEM3>>>(
        qh, ql, wih, wil, nullptr, fq, INNER);
    gemm_mma<640, false, true><<<dim3(INNER / 128, MK / 128), 256, SMEM3>>>(
        kh, kl, wih, wil, nullptr, fk, INNER);
    gemm_mma<640, false, true><<<dim3(INNER / 128, MK / 128), 256, SMEM3>>>(
        vh, vl, wih, wil, nullptr, fv, INNER);

    // 4) attention combine -> fp16 o_inner
    combine_kernel<<<QLEN, 256>>>(fq, fk, fv, vscale, cscale, oo);

    // 5) output projection: single-pass fp16 + bias (linear stage, not amplified)
    gemm_mma<512, true, false><<<dim3(DDIM / 128, MQ / 128), 256, SMEM1>>>(
        oo, nullptr, wof, nullptr, b_out, out, DDIM);
}

// round 5
// speedup vs baseline: 3.5797x; 1.0321x over previous
#include <cuda_runtime.h>
#include <cuda_bf16.h>
#include <cuda_fp16.h>
#include <math.h>
#include <stdint.h>

// ---------------------------------------------------------------------------
// dims fixed for this dataset
#define QLEN   8192
#define NWAY   5
#define DDIM   640
#define INNER  512
#define HEADS  8
#define DH     64
#define MQ     (QLEN * NWAY)   // 40960
#define MK     QLEN            // 8192

// ------------------------- scratch (device globals) ------------------------
__device__ __align__(256) float g_fq[(size_t)MQ * INNER];
__device__ __align__(256) float g_fk[(size_t)MK * INNER];
__device__ __align__(256) __nv_bfloat16 g_qh[(size_t)MQ * DDIM];
__device__ __align__(256) __nv_bfloat16 g_ql[(size_t)MQ * DDIM];
__device__ __align__(256) __nv_bfloat16 g_kh[(size_t)MK * DDIM];
__device__ __align__(256) __nv_bfloat16 g_kl[(size_t)MK * DDIM];
__device__ __align__(256) __half        g_vhf[(size_t)MK * DDIM];     // fp16 LN(v)
__device__ __align__(256) __half        g_fvh[(size_t)MK * INNER];    // fp16 f_v
__device__ __align__(256) __half        g_G  [(size_t)MK * HEADS * DDIM]; // (q,h,d)
__device__ __align__(256) __nv_bfloat16 g_wi_h[(size_t)DDIM * INNER];   // K x N
__device__ __align__(256) __nv_bfloat16 g_wi_l[(size_t)DDIM * INNER];
__device__ __align__(256) __half        g_wi_f[(size_t)DDIM * INNER];   // fp16 W_in
__device__ __align__(256) __half        g_wo_f[(size_t)INNER * DDIM];   // fp16 W_out

// ------------------------- helpers -----------------------------------------
__device__ __forceinline__ uint32_t smem_u32(const void* p) {
    uint32_t a;
    asm("{ .reg .u64 t; cvta.to.shared.u64 t, %1; cvt.u32.u64 %0, t; }"
        : "=r"(a) : "l"(p));
    return a;
}
__device__ __forceinline__ void cp16(uint32_t dst, const void* src) {
    asm volatile(
        "{ .reg .u64 g; cvta.to.global.u64 g, %1;"
        " cp.async.cg.shared.global [%0], [g], 16; }"
        :: "r"(dst), "l"(src) : "memory");
}
__device__ __forceinline__ void cp_commit() {
    asm volatile("cp.async.commit_group;" ::: "memory");
}
__device__ __forceinline__ void cp_wait0() {
    asm volatile("cp.async.wait_group 0;" ::: "memory");
}
__device__ __forceinline__ void cp_wait1() {
    asm volatile("cp.async.wait_group 1;" ::: "memory");
}
__device__ __forceinline__ void cp_wait2() {
    asm volatile("cp.async.wait_group 2;" ::: "memory");
}
__device__ __forceinline__ void ldsm_x4(uint32_t* r, uint32_t addr) {
    asm volatile("ldmatrix.sync.aligned.m8n8.x4.shared.b16 {%0,%1,%2,%3}, [%4];"
                 : "=r"(r[0]), "=r"(r[1]), "=r"(r[2]), "=r"(r[3]) : "r"(addr));
}
__device__ __forceinline__ void ldsm_x4t(uint32_t* r, uint32_t addr) {
    asm volatile("ldmatrix.sync.aligned.m8n8.x4.trans.shared.b16 {%0,%1,%2,%3}, [%4];"
                 : "=r"(r[0]), "=r"(r[1]), "=r"(r[2]), "=r"(r[3]) : "r"(addr));
}
__device__ __forceinline__ void mma_bf16(float* c, const uint32_t* a,
                                         uint32_t b0, uint32_t b1) {
    asm volatile(
        "mma.sync.aligned.m16n8k16.row.col.f32.bf16.bf16.f32 "
        "{%0,%1,%2,%3}, {%4,%5,%6,%7}, {%8,%9}, {%0,%1,%2,%3};"
        : "+f"(c[0]), "+f"(c[1]), "+f"(c[2]), "+f"(c[3])
        : "r"(a[0]), "r"(a[1]), "r"(a[2]), "r"(a[3]), "r"(b0), "r"(b1));
}
__device__ __forceinline__ void mma_fp16(float* c, const uint32_t* a,
                                         uint32_t b0, uint32_t b1) {
    asm volatile(
        "mma.sync.aligned.m16n8k16.row.col.f32.f16.f16.f32 "
        "{%0,%1,%2,%3}, {%4,%5,%6,%7}, {%8,%9}, {%0,%1,%2,%3};"
        : "+f"(c[0]), "+f"(c[1]), "+f"(c[2]), "+f"(c[3])
        : "r"(a[0]), "r"(a[1]), "r"(a[2]), "r"(a[3]), "r"(b0), "r"(b1));
}

// ------------------------- LN + bf16 split / fp16 --------------------------
__global__ __launch_bounds__(256) void ln_split_kernel(
    const float* __restrict__ X, const float* __restrict__ g,
    const float* __restrict__ b, __nv_bfloat16* __restrict__ Xh,
    __nv_bfloat16* __restrict__ Xl, int rows)
{
    int row  = blockIdx.x * 8 + (threadIdx.x >> 5);
    int lane = threadIdx.x & 31;
    if (row >= rows) return;
    const float* x = X + (size_t)row * DDIM;
    float v[20];
    float s = 0.f, s2 = 0.f;
#pragma unroll
    for (int i = 0; i < 20; i++) {
        v[i] = x[lane + i * 32];
        s += v[i]; s2 += v[i] * v[i];
    }
#pragma unroll
    for (int o = 16; o > 0; o >>= 1) {
        s  += __shfl_xor_sync(0xffffffffu, s,  o);
        s2 += __shfl_xor_sync(0xffffffffu, s2, o);
    }
    float m   = s * (1.f / DDIM);
    float var = s2 * (1.f / DDIM) - m * m;
    float rs  = rsqrtf(var + 1e-5f);
#pragma unroll
    for (int i = 0; i < 20; i++) {
        int c = lane + i * 32;
        float xn = (v[i] - m) * rs * g[c] + b[c];
        __nv_bfloat16 h = __float2bfloat16(xn);
        Xh[(size_t)row * DDIM + c] = h;
        Xl[(size_t)row * DDIM + c] = __float2bfloat16(xn - __bfloat162float(h));
    }
}
__global__ __launch_bounds__(256) void ln_half_kernel(
    const float* __restrict__ X, const float* __restrict__ g,
    const float* __restrict__ b, __half* __restrict__ Xf, int rows)
{
    int row  = blockIdx.x * 8 + (threadIdx.x >> 5);
    int lane = threadIdx.x & 31;
    if (row >= rows) return;
    const float* x = X + (size_t)row * DDIM;
    float v[20];
    float s = 0.f, s2 = 0.f;
#pragma unroll
    for (int i = 0; i < 20; i++) {
        v[i] = x[lane + i * 32];
        s += v[i]; s2 += v[i] * v[i];
    }
#pragma unroll
    for (int o = 16; o > 0; o >>= 1) {
        s  += __shfl_xor_sync(0xffffffffu, s,  o);
        s2 += __shfl_xor_sync(0xffffffffu, s2, o);
    }
    float m   = s * (1.f / DDIM);
    float var = s2 * (1.f / DDIM) - m * m;
    float rs  = rsqrtf(var + 1e-5f);
#pragma unroll
    for (int i = 0; i < 20; i++) {
        int c = lane + i * 32;
        Xf[(size_t)row * DDIM + c] = __float2half((v[i] - m) * rs * g[c] + b[c]);
    }
}

// ------------------------- W prep -------------------------------------------
__global__ __launch_bounds__(256) void wsplit_kernel(
    const float* __restrict__ W, __nv_bfloat16* __restrict__ Th,
    __nv_bfloat16* __restrict__ Tl, __half* __restrict__ Tf, int total)
{
    int idx = blockIdx.x * 256 + threadIdx.x;
    if (idx >= total) return;
    float w = W[idx];
    __nv_bfloat16 h = __float2bfloat16(w);
    Th[idx] = h;
    Tl[idx] = __float2bfloat16(w - __bfloat162float(h));
    if (Tf) Tf[idx] = __float2half(w);
}
__global__ __launch_bounds__(256) void whalf_kernel(
    const float* __restrict__ W, __half* __restrict__ T, int total)
{
    int idx = blockIdx.x * 256 + threadIdx.x;
    if (idx >= total) return;
    T[idx] = __float2half(W[idx]);
}

// ------------------------- GEMM via mma.sync --------------------------------
// SPLIT3=true : C = (Ah+Al) @ (Bh+Bl) 3-pass bf16 (drops AlBl), fp32 accum.
// SPLIT3=false: C = Ah @ Bh single-pass fp16.
// OUTH: write fp16 C. HB: head-batched (blockIdx.z = head, A +z*64 cols,
// B +z*64 rows, C +z*640 cols).
// CTA tile 128x128, BK=64, 3-stage cp.async. 8 warps (2m x 4n), warp 64x32.
#define ASZ 16384
template <int KD, bool BIAS, bool SPLIT3, bool OUTH, bool HB>
__global__ __launch_bounds__(256, SPLIT3 ? 1 : 2) void gemm_mma(
    const void* __restrict__ Ah_, const void* __restrict__ Al_,
    const void* __restrict__ Bh_, const void* __restrict__ Bl_,
    const float* __restrict__ bias, void* __restrict__ C_,
    int lda, int ldb, int ldc)
{
    constexpr int NC   = KD / 64;
    constexpr int STG  = SPLIT3 ? 65536 : 32768;
    constexpr int BOFF = SPLIT3 ? 32768 : 16384;
    const int z = HB ? blockIdx.z : 0;
    const uint16_t* Ah = (const uint16_t*)Ah_ + (HB ? z * 64 : 0);
    const uint16_t* Al = (const uint16_t*)Al_;
    const uint16_t* Bh = (const uint16_t*)Bh_ + (HB ? (size_t)z * 64 * ldb : 0);
    const uint16_t* Bl = (const uint16_t*)Bl_;

    extern __shared__ char smraw[];
    const uint32_t sb = (smem_u32(smraw) + 127u) & ~127u;

    const int tid  = threadIdx.x;
    const int lane = tid & 31;
    const int wid  = tid >> 5;
    const int bm   = blockIdx.y * 128;
    const int bn   = blockIdx.x * 128;
    const int wm   = (wid >> 2) * 64;
    const int wn   = (wid & 3) * 32;

    float acc[4][4][4];
#pragma unroll
    for (int i = 0; i < 4; i++)
#pragma unroll
        for (int j = 0; j < 4; j++)
#pragma unroll
            for (int t = 0; t < 4; t++) acc[i][j][t] = 0.f;

    auto load_stage = [&](int s, int c) {
        const uint32_t base = sb + (uint32_t)s * STG;
        const int kb = c * 64;
#pragma unroll
        for (int u = tid; u < 1024; u += 256) {
            int r = u >> 3, kc = u & 7;
            uint32_t off = (uint32_t)(r * 128 + kc * 16) ^ (uint32_t)((r & 7) << 4);
            const size_t gi = (size_t)(bm + r) * lda + kb + kc * 8;
            cp16(base + off, Ah + gi);
            if (SPLIT3) cp16(base + ASZ + off, Al + gi);
        }
#pragma unroll
        for (int u = tid; u < 1024; u += 256) {
            int kk = u >> 4, nc2 = u & 15;
            uint32_t off = (uint32_t)(kk * 256 + nc2 * 16) ^ (uint32_t)((kk & 7) << 4);
            const size_t gi = (size_t)(kb + kk) * ldb + bn + nc2 * 8;
            cp16(base + BOFF + off, Bh + gi);
            if (SPLIT3) cp16(base + BOFF + ASZ + off, Bl + gi);
        }
        cp_commit();
    };

    load_stage(0, 0);
    if (NC > 1) load_stage(1, 1);

    const int arow   = wm + (lane & 15);
    const int acol16 = (lane >> 4) * 16;
    const int brow0  = ((lane >> 3) & 1) * 8 + (lane & 7);
    const int bnc    = wn + (lane >> 4) * 8;

    int sidx = 0;
    for (int c = 0; c < NC; c++) {
        if (c + 2 < NC) {
            int ns = sidx + 2; if (ns >= 3) ns -= 3;
            load_stage(ns, c + 2);
            cp_wait2();
        } else if (c + 1 < NC) {
            cp_wait1();
        } else {
            cp_wait0();
        }
        __syncthreads();

        const uint32_t base = sb + (uint32_t)sidx * STG;
#pragma unroll
        for (int ks = 0; ks < 4; ks++) {
            uint32_t ahf[4][4], bhf[8];
#pragma unroll
            for (int mf = 0; mf < 4; mf++) {
                int r = arow + mf * 16;
                uint32_t off = (uint32_t)(r * 128 + ks * 32 + acol16)
                             ^ (uint32_t)((r & 7) << 4);
                ldsm_x4(ahf[mf], base + off);
            }
#pragma unroll
            for (int g2 = 0; g2 < 2; g2++) {
                int kk = ks * 16 + brow0;
                int nn = bnc + g2 * 16;
                uint32_t off = (uint32_t)(kk * 256 + nn * 2)
                             ^ (uint32_t)((kk & 7) << 4);
                ldsm_x4t(&bhf[g2 * 4], base + BOFF + off);
            }
            if (SPLIT3) {
                uint32_t alf[4][4], blf[8];
#pragma unroll
                for (int mf = 0; mf < 4; mf++) {
                    int r = arow + mf * 16;
                    uint32_t off = (uint32_t)(r * 128 + ks * 32 + acol16)
                                 ^ (uint32_t)((r & 7) << 4);
                    ldsm_x4(alf[mf], base + ASZ + off);
                }
#pragma unroll
                for (int g2 = 0; g2 < 2; g2++) {
                    int kk = ks * 16 + brow0;
                    int nn = bnc + g2 * 16;
                    uint32_t off = (uint32_t)(kk * 256 + nn * 2)
                                 ^ (uint32_t)((kk & 7) << 4);
                    ldsm_x4t(&blf[g2 * 4], base + BOFF + ASZ + off);
                }
#pragma unroll
                for (int mf = 0; mf < 4; mf++)
#pragma unroll
                    for (int nf = 0; nf < 4; nf++) {
                        mma_bf16(acc[mf][nf], ahf[mf], bhf[nf * 2], bhf[nf * 2 + 1]);
                        mma_bf16(acc[mf][nf], ahf[mf], blf[nf * 2], blf[nf * 2 + 1]);
                        mma_bf16(acc[mf][nf], alf[mf], bhf[nf * 2], bhf[nf * 2 + 1]);
                    }
            } else {
#pragma unroll
                for (int mf = 0; mf < 4; mf++)
#pragma unroll
                    for (int nf = 0; nf < 4; nf++)
                        mma_fp16(acc[mf][nf], ahf[mf], bhf[nf * 2], bhf[nf * 2 + 1]);
            }
        }
        __syncthreads();
        sidx++; if (sidx == 3) sidx = 0;
    }

    // ---- epilogue ----
    const int r0 = bm + wm + (lane >> 2);
    const int c0 = bn + wn + (lane & 3) * 2;
    if (OUTH) {
        __half* Ch = (__half*)C_ + (HB ? z * 640 : 0);
#pragma unroll
        for (int mf = 0; mf < 4; mf++)
#pragma unroll
            for (int nf = 0; nf < 4; nf++) {
                int gr0 = r0 + mf * 16;
                int gc  = c0 + nf * 8;
                __half2 v0 = __floats2half2_rn(acc[mf][nf][0], acc[mf][nf][1]);
                __half2 v1 = __floats2half2_rn(acc[mf][nf][2], acc[mf][nf][3]);
                *reinterpret_cast<__half2*>(Ch + (size_t)gr0 * ldc + gc)       = v0;
                *reinterpret_cast<__half2*>(Ch + (size_t)(gr0 + 8) * ldc + gc) = v1;
            }
    } else {
        float* C = (float*)C_;
#pragma unroll
        for (int mf = 0; mf < 4; mf++)
#pragma unroll
            for (int nf = 0; nf < 4; nf++) {
                int gr0 = r0 + mf * 16;
                int gc  = c0 + nf * 8;
                float b0 = 0.f, b1 = 0.f;
                if (BIAS) { b0 = bias[gc]; b1 = bias[gc + 1]; }
                float2 v0 = make_float2(acc[mf][nf][0] + b0, acc[mf][nf][1] + b1);
                float2 v1 = make_float2(acc[mf][nf][2] + b0, acc[mf][nf][3] + b1);
                *reinterpret_cast<float2*>(C + (size_t)gr0 * ldc + gc)       = v0;
                *reinterpret_cast<float2*>(C + (size_t)(gr0 + 8) * ldc + gc) = v1;
            }
    }
}

// ------------------------- fused combine + output assembly ------------------
// Block per q. Warp h computes c[h][n] from f_q/f_k; then all threads build
// out[q,n,:] = b_out + sum_h c[h][n] * G[q,h,:].
__global__ __launch_bounds__(256) void combine_out_kernel(
    const float* __restrict__ fq, const float* __restrict__ fk,
    const __half* __restrict__ G, const float* __restrict__ vs_p,
    const float* __restrict__ cs_p, const float* __restrict__ b_out,
    float* __restrict__ out)
{
    const int q    = blockIdx.x;
    const int tid  = threadIdx.x;
    const int h    = tid >> 5;
    const int lane = tid & 31;
    const float vscale = *vs_p;
    const float cscale = *cs_p;

    __shared__ float c_sm[HEADS][NWAY];
    __shared__ __half G_sm[HEADS * DDIM];

    // stage G[q] into smem (coalesced float4 = 8 halves)
    {
        const float4* Gq = reinterpret_cast<const float4*>(G + (size_t)q * HEADS * DDIM);
        float4* Gs = reinterpret_cast<float4*>(G_sm);
#pragma unroll
        for (int i = tid; i < HEADS * DDIM / 8; i += 256) Gs[i] = Gq[i];
    }

    const float* fkp = fk + (size_t)q * INNER + h * DH;
    const float k0 = fkp[lane], k1 = fkp[lane + 32];

    float sk = k0 + k1, sk2 = k0 * k0 + k1 * k1;
#pragma unroll
    for (int o = 16; o > 0; o >>= 1) {
        sk  += __shfl_xor_sync(0xffffffffu, sk,  o);
        sk2 += __shfl_xor_sync(0xffffffffu, sk2, o);
    }
    const float mk = sk * (1.f / DH);
    const float nk = sqrtf(sk2);
    const float ek0 = k0 - mk, ek1 = k1 - mk;
    float skc = ek0 * ek0 + ek1 * ek1;
#pragma unroll
    for (int o = 16; o > 0; o >>= 1)
        skc += __shfl_xor_sync(0xffffffffu, skc, o);
    const float vark = skc * (1.f / DH);

    float base[NWAY], vw[NWAY];
    float vwsum = 0.f;
#pragma unroll
    for (int n = 0; n < NWAY; n++) {
        const float* fqp = fq + ((size_t)q * NWAY + n) * INNER + h * DH;
        const float a0 = fqp[lane], a1 = fqp[lane + 32];
        float s = a0 + a1;
#pragma unroll
        for (int o = 16; o > 0; o >>= 1)
            s += __shfl_xor_sync(0xffffffffu, s, o);
        const float mq = s * (1.f / DH);
        const float e0 = a0 - mq, e1 = a1 - mq;
        float s2 = a0 * a0 + a1 * a1;
        float d  = a0 * k0 + a1 * k1;
        float s2c = e0 * e0 + e1 * e1;
        float dc  = e0 * ek0 + e1 * ek1;
#pragma unroll
        for (int o = 16; o > 0; o >>= 1) {
            s2  += __shfl_xor_sync(0xffffffffu, s2,  o);
            d   += __shfl_xor_sync(0xffffffffu, d,   o);
            s2c += __shfl_xor_sync(0xffffffffu, s2c, o);
            dc  += __shfl_xor_sync(0xffffffffu, dc,  o);
        }
        const float nq   = sqrtf(s2);
        const float varq = s2c * (1.f / DH);
        const float cosd = d / (nq * nk);
        const float w    = 1.f / (fabsf(vark - varq) + 1e-6f);
        vw[n]  = w;
        vwsum += w;
        const float cov  = dc * (1.f / (DH + 1e-6f));
        const float sig  = 1.f / (1.f + expf(-cov));
        base[n] = cosd + cscale * sig;
    }
    const float inv = 1.f / (vwsum + 1e-6f);
    if (lane < NWAY)
        c_sm[h][lane] = base[lane] + vscale * vw[lane] * inv;
    __syncthreads();

    // assembly: 5 x 640 outputs
    float* oq = out + (size_t)q * NWAY * DDIM;
    for (int idx = tid; idx < NWAY * DDIM; idx += 256) {
        int n = idx / DDIM, d = idx - n * DDIM;
        float acc = b_out[d];
#pragma unroll
        for (int hh = 0; hh < HEADS; hh++)
            acc += c_sm[hh][n] * __half2float(G_sm[hh * DDIM + d]);
        oq[idx] = acc;
    }
}

// ---------------------------------------------------------------------------
extern "C" void kernel_launch(void* const* d_in, const int* in_sizes, int n_in,
                              void* d_out, int out_size)
{
    const float* q      = (const float*)d_in[0];
    const float* k      = (const float*)d_in[1];
    const float* v      = (const float*)d_in[2];
    const float* ln_g   = (const float*)d_in[3];
    const float* ln_b   = (const float*)d_in[4];
    const float* W_in   = (const float*)d_in[5];
    const float* W_out  = (const float*)d_in[6];
    const float* b_out  = (const float*)d_in[7];
    const float* vscale = (const float*)d_in[8];
    const float* cscale = (const float*)d_in[9];
    float* out = (float*)d_out;

    float *fq, *fk;
    __nv_bfloat16 *qh, *ql, *kh, *kl, *wih, *wil;
    __half *vhf, *fvh, *G, *wif, *wof;
    cudaGetSymbolAddress((void**)&fq,  g_fq);
    cudaGetSymbolAddress((void**)&fk,  g_fk);
    cudaGetSymbolAddress((void**)&qh,  g_qh);
    cudaGetSymbolAddress((void**)&ql,  g_ql);
    cudaGetSymbolAddress((void**)&kh,  g_kh);
    cudaGetSymbolAddress((void**)&kl,  g_kl);
    cudaGetSymbolAddress((void**)&vhf, g_vhf);
    cudaGetSymbolAddress((void**)&fvh, g_fvh);
    cudaGetSymbolAddress((void**)&G,   g_G);
    cudaGetSymbolAddress((void**)&wih, g_wi_h);
    cudaGetSymbolAddress((void**)&wil, g_wi_l);
    cudaGetSymbolAddress((void**)&wif, g_wi_f);
    cudaGetSymbolAddress((void**)&wof, g_wo_f);

    const int SMEM3 = 3 * 65536 + 128;   // 3-stage split3
    const int SMEM1 = 3 * 32768 + 128;   // 3-stage fp16 single
    const int SMEMG = 32768 + 128;       // 1 chunk (KD=64)
    cudaFuncSetAttribute((const void*)gemm_mma<640, false, true,  false, false>,
                         cudaFuncAttributeMaxDynamicSharedMemorySize, SMEM3);
    cudaFuncSetAttribute((const void*)gemm_mma<640, false, false, true,  false>,
                         cudaFuncAttributeMaxDynamicSharedMemorySize, SMEM1);
    cudaFuncSetAttribute((const void*)gemm_mma<64,  false, false, true,  true>,
                         cudaFuncAttributeMaxDynamicSharedMemorySize, SMEMG);

    // 1) LN: q/k split bf16, v -> fp16
    ln_split_kernel<<<MQ / 8, 256>>>(q, ln_g, ln_b, qh, ql, MQ);
    ln_split_kernel<<<MK / 8, 256>>>(k, ln_g, ln_b, kh, kl, MK);
    ln_half_kernel <<<MK / 8, 256>>>(v, ln_g, ln_b, vhf, MK);

    // 2) weight prep
    wsplit_kernel<<<(DDIM * INNER + 255) / 256, 256>>>(W_in, wih, wil, wif,
                                                       DDIM * INNER);
    whalf_kernel<<<(INNER * DDIM + 255) / 256, 256>>>(W_out, wof, INNER * DDIM);

    // 3) q/k projections: 3-pass bf16-split (combine-amplified paths)
    gemm_mma<640, false, true, false, false>
        <<<dim3(INNER / 128, MQ / 128), 256, SMEM3>>>(
            qh, ql, wih, wil, nullptr, fq, DDIM, INNER, INNER);
    gemm_mma<640, false, true, false, false>
        <<<dim3(INNER / 128, MK / 128), 256, SMEM3>>>(
            kh, kl, wih, wil, nullptr, fk, DDIM, INNER, INNER);

    // 4) v projection: single-pass fp16 -> fp16 f_v (linear path)
    gemm_mma<640, false, false, true, false>
        <<<dim3(INNER / 128, MK / 128), 256, SMEM1>>>(
            vhf, nullptr, wif, nullptr, nullptr, fvh, DDIM, INNER, INNER);

    // 5) per-head projected V: G[q,h,:] = f_v_head @ W_out_head (fp16, K=64)
    gemm_mma<64, false, false, true, true>
        <<<dim3(DDIM / 128, MK / 128, HEADS), 256, SMEMG>>>(
            fvh, nullptr, wof, nullptr, nullptr, G, INNER, DDIM, HEADS * DDIM);

    // 6) fused combine + output assembly
    combine_out_kernel<<<QLEN, 256>>>(fq, fk, G, vscale, cscale, b_out, out);
}

// round 6
// speedup vs baseline: 3.7848x; 1.0573x over previous
#include <cuda_runtime.h>
#include <cuda_bf16.h>
#include <cuda_fp16.h>
#include <math.h>
#include <stdint.h>

// ---------------------------------------------------------------------------
// dims fixed for this dataset
#define QLEN   8192
#define NWAY   5
#define DDIM   640
#define INNER  512
#define HEADS  8
#define DH     64
#define MQ     (QLEN * NWAY)   // 40960
#define MK     QLEN            // 8192

// ------------------------- scratch (device globals) ------------------------
__device__ __align__(256) float g_fk[(size_t)MK * INNER];
__device__ __align__(256) float g_R  [(size_t)MQ * HEADS * 3];   // S1,S2,S3
__device__ __align__(256) float g_kst[(size_t)MK * HEADS * 3];   // mk,nk,vark
__device__ __align__(256) __nv_bfloat16 g_qh[(size_t)MQ * DDIM];
__device__ __align__(256) __nv_bfloat16 g_ql[(size_t)MQ * DDIM];
__device__ __align__(256) __nv_bfloat16 g_kh[(size_t)MK * DDIM];
__device__ __align__(256) __nv_bfloat16 g_kl[(size_t)MK * DDIM];
__device__ __align__(256) __half        g_vhf[(size_t)MK * DDIM];     // fp16 LN(v)
__device__ __align__(256) __half        g_fvh[(size_t)MK * INNER];    // fp16 f_v
__device__ __align__(256) __half        g_G  [(size_t)MK * HEADS * DDIM]; // (q,h,d)
__device__ __align__(256) __nv_bfloat16 g_wi_h[(size_t)DDIM * INNER];   // K x N
__device__ __align__(256) __nv_bfloat16 g_wi_l[(size_t)DDIM * INNER];
__device__ __align__(256) __half        g_wi_f[(size_t)DDIM * INNER];   // fp16 W_in
__device__ __align__(256) __half        g_wo_f[(size_t)INNER * DDIM];   // fp16 W_out

// ------------------------- helpers -----------------------------------------
__device__ __forceinline__ uint32_t smem_u32(const void* p) {
    uint32_t a;
    asm("{ .reg .u64 t; cvta.to.shared.u64 t, %1; cvt.u32.u64 %0, t; }"
        : "=r"(a) : "l"(p));
    return a;
}
__device__ __forceinline__ void cp16(uint32_t dst, const void* src) {
    asm volatile(
        "{ .reg .u64 g; cvta.to.global.u64 g, %1;"
        " cp.async.cg.shared.global [%0], [g], 16; }"
        :: "r"(dst), "l"(src) : "memory");
}
__device__ __forceinline__ void cp_commit() {
    asm volatile("cp.async.commit_group;" ::: "memory");
}
__device__ __forceinline__ void cp_wait0() {
    asm volatile("cp.async.wait_group 0;" ::: "memory");
}
__device__ __forceinline__ void cp_wait1() {
    asm volatile("cp.async.wait_group 1;" ::: "memory");
}
__device__ __forceinline__ void cp_wait2() {
    asm volatile("cp.async.wait_group 2;" ::: "memory");
}
__device__ __forceinline__ void ldsm_x4(uint32_t* r, uint32_t addr) {
    asm volatile("ldmatrix.sync.aligned.m8n8.x4.shared.b16 {%0,%1,%2,%3}, [%4];"
                 : "=r"(r[0]), "=r"(r[1]), "=r"(r[2]), "=r"(r[3]) : "r"(addr));
}
__device__ __forceinline__ void ldsm_x4t(uint32_t* r, uint32_t addr) {
    asm volatile("ldmatrix.sync.aligned.m8n8.x4.trans.shared.b16 {%0,%1,%2,%3}, [%4];"
                 : "=r"(r[0]), "=r"(r[1]), "=r"(r[2]), "=r"(r[3]) : "r"(addr));
}
__device__ __forceinline__ void mma_bf16(float* c, const uint32_t* a,
                                         uint32_t b0, uint32_t b1) {
    asm volatile(
        "mma.sync.aligned.m16n8k16.row.col.f32.bf16.bf16.f32 "
        "{%0,%1,%2,%3}, {%4,%5,%6,%7}, {%8,%9}, {%0,%1,%2,%3};"
        : "+f"(c[0]), "+f"(c[1]), "+f"(c[2]), "+f"(c[3])
        : "r"(a[0]), "r"(a[1]), "r"(a[2]), "r"(a[3]), "r"(b0), "r"(b1));
}
__device__ __forceinline__ void mma_fp16(float* c, const uint32_t* a,
                                         uint32_t b0, uint32_t b1) {
    asm volatile(
        "mma.sync.aligned.m16n8k16.row.col.f32.f16.f16.f32 "
        "{%0,%1,%2,%3}, {%4,%5,%6,%7}, {%8,%9}, {%0,%1,%2,%3};"
        : "+f"(c[0]), "+f"(c[1]), "+f"(c[2]), "+f"(c[3])
        : "r"(a[0]), "r"(a[1]), "r"(a[2]), "r"(a[3]), "r"(b0), "r"(b1));
}

// ------------------------- LN + bf16 split / fp16 --------------------------
__global__ __launch_bounds__(256) void ln_split_kernel(
    const float* __restrict__ X, const float* __restrict__ g,
    const float* __restrict__ b, __nv_bfloat16* __restrict__ Xh,
    __nv_bfloat16* __restrict__ Xl, int rows)
{
    int row  = blockIdx.x * 8 + (threadIdx.x >> 5);
    int lane = threadIdx.x & 31;
    if (row >= rows) return;
    const float* x = X + (size_t)row * DDIM;
    float v[20];
    float s = 0.f, s2 = 0.f;
#pragma unroll
    for (int i = 0; i < 20; i++) {
        v[i] = x[lane + i * 32];
        s += v[i]; s2 += v[i] * v[i];
    }
#pragma unroll
    for (int o = 16; o > 0; o >>= 1) {
        s  += __shfl_xor_sync(0xffffffffu, s,  o);
        s2 += __shfl_xor_sync(0xffffffffu, s2, o);
    }
    float m   = s * (1.f / DDIM);
    float var = s2 * (1.f / DDIM) - m * m;
    float rs  = rsqrtf(var + 1e-5f);
#pragma unroll
    for (int i = 0; i < 20; i++) {
        int c = lane + i * 32;
        float xn = (v[i] - m) * rs * g[c] + b[c];
        __nv_bfloat16 h = __float2bfloat16(xn);
        Xh[(size_t)row * DDIM + c] = h;
        Xl[(size_t)row * DDIM + c] = __float2bfloat16(xn - __bfloat162float(h));
    }
}
__global__ __launch_bounds__(256) void ln_half_kernel(
    const float* __restrict__ X, const float* __restrict__ g,
    const float* __restrict__ b, __half* __restrict__ Xf, int rows)
{
    int row  = blockIdx.x * 8 + (threadIdx.x >> 5);
    int lane = threadIdx.x & 31;
    if (row >= rows) return;
    const float* x = X + (size_t)row * DDIM;
    float v[20];
    float s = 0.f, s2 = 0.f;
#pragma unroll
    for (int i = 0; i < 20; i++) {
        v[i] = x[lane + i * 32];
        s += v[i]; s2 += v[i] * v[i];
    }
#pragma unroll
    for (int o = 16; o > 0; o >>= 1) {
        s  += __shfl_xor_sync(0xffffffffu, s,  o);
        s2 += __shfl_xor_sync(0xffffffffu, s2, o);
    }
    float m   = s * (1.f / DDIM);
    float var = s2 * (1.f / DDIM) - m * m;
    float rs  = rsqrtf(var + 1e-5f);
#pragma unroll
    for (int i = 0; i < 20; i++) {
        int c = lane + i * 32;
        Xf[(size_t)row * DDIM + c] = __float2half((v[i] - m) * rs * g[c] + b[c]);
    }
}

// ------------------------- W prep -------------------------------------------
__global__ __launch_bounds__(256) void wsplit_kernel(
    const float* __restrict__ W, __nv_bfloat16* __restrict__ Th,
    __nv_bfloat16* __restrict__ Tl, __half* __restrict__ Tf, int total)
{
    int idx = blockIdx.x * 256 + threadIdx.x;
    if (idx >= total) return;
    float w = W[idx];
    __nv_bfloat16 h = __float2bfloat16(w);
    Th[idx] = h;
    Tl[idx] = __float2bfloat16(w - __bfloat162float(h));
    if (Tf) Tf[idx] = __float2half(w);
}
__global__ __launch_bounds__(256) void whalf_kernel(
    const float* __restrict__ W, __half* __restrict__ T, int total)
{
    int idx = blockIdx.x * 256 + threadIdx.x;
    if (idx >= total) return;
    T[idx] = __float2half(W[idx]);
}

// ------------------------- k stats: mk, nk, vark ----------------------------
// warp (q) x 8 heads per block: warp h handles (blockIdx.x, h)
__global__ __launch_bounds__(256) void kstats_kernel(
    const float* __restrict__ fk, float* __restrict__ kst)
{
    const int q    = blockIdx.x;
    const int h    = threadIdx.x >> 5;
    const int lane = threadIdx.x & 31;
    const float* fkp = fk + (size_t)q * INNER + h * DH;
    const float k0 = fkp[lane], k1 = fkp[lane + 32];
    float sk = k0 + k1, sk2 = k0 * k0 + k1 * k1;
#pragma unroll
    for (int o = 16; o > 0; o >>= 1) {
        sk  += __shfl_xor_sync(0xffffffffu, sk,  o);
        sk2 += __shfl_xor_sync(0xffffffffu, sk2, o);
    }
    const float mk = sk * (1.f / DH);
    const float ek0 = k0 - mk, ek1 = k1 - mk;
    float skc = ek0 * ek0 + ek1 * ek1;
#pragma unroll
    for (int o = 16; o > 0; o >>= 1)
        skc += __shfl_xor_sync(0xffffffffu, skc, o);
    if (lane == 0) {
        float* p = kst + ((size_t)q * HEADS + h) * 3;
        p[0] = mk;
        p[1] = sqrtf(sk2);
        p[2] = skc * (1.f / DH);
    }
}

// ------------------------- GEMM via mma.sync --------------------------------
// SPLIT3: 3-pass bf16 split (drops AlBl). else single-pass fp16.
// OUTH: fp16 C. HB: head-batched (blockIdx.z). RED: no C write; instead
// epilogue computes per-(row, head) S1=Σfq, S2=Σfq², S3=Σfq·fk and writes
// Rbuf[row][head][3] (q-projection fusion; needs FK = f_k fp32, ld=INNER).
#define ASZ 16384
template <int KD, bool BIAS, bool SPLIT3, bool OUTH, bool HB, bool RED>
__global__ __launch_bounds__(256, SPLIT3 ? 1 : 2) void gemm_mma(
    const void* __restrict__ Ah_, const void* __restrict__ Al_,
    const void* __restrict__ Bh_, const void* __restrict__ Bl_,
    const float* __restrict__ bias, void* __restrict__ C_,
    const float* __restrict__ FK, float* __restrict__ Rbuf,
    int lda, int ldb, int ldc)
{
    constexpr int NC   = KD / 64;
    constexpr int STG  = SPLIT3 ? 65536 : 32768;
    constexpr int BOFF = SPLIT3 ? 32768 : 16384;
    const int z = HB ? blockIdx.z : 0;
    const uint16_t* Ah = (const uint16_t*)Ah_ + (HB ? z * 64 : 0);
    const uint16_t* Al = (const uint16_t*)Al_;
    const uint16_t* Bh = (const uint16_t*)Bh_ + (HB ? (size_t)z * 64 * ldb : 0);
    const uint16_t* Bl = (const uint16_t*)Bl_;

    extern __shared__ char smraw[];
    const uint32_t sb = (smem_u32(smraw) + 127u) & ~127u;

    const int tid  = threadIdx.x;
    const int lane = tid & 31;
    const int wid  = tid >> 5;
    const int bm   = blockIdx.y * 128;
    const int bn   = blockIdx.x * 128;
    const int wm   = (wid >> 2) * 64;
    const int wn   = (wid & 3) * 32;

    float acc[4][4][4];
#pragma unroll
    for (int i = 0; i < 4; i++)
#pragma unroll
        for (int j = 0; j < 4; j++)
#pragma unroll
            for (int t = 0; t < 4; t++) acc[i][j][t] = 0.f;

    auto load_stage = [&](int s, int c) {
        const uint32_t base = sb + (uint32_t)s * STG;
        const int kb = c * 64;
#pragma unroll
        for (int u = tid; u < 1024; u += 256) {
            int r = u >> 3, kc = u & 7;
            uint32_t off = (uint32_t)(r * 128 + kc * 16) ^ (uint32_t)((r & 7) << 4);
            const size_t gi = (size_t)(bm + r) * lda + kb + kc * 8;
            cp16(base + off, Ah + gi);
            if (SPLIT3) cp16(base + ASZ + off, Al + gi);
        }
#pragma unroll
        for (int u = tid; u < 1024; u += 256) {
            int kk = u >> 4, nc2 = u & 15;
            uint32_t off = (uint32_t)(kk * 256 + nc2 * 16) ^ (uint32_t)((kk & 7) << 4);
            const size_t gi = (size_t)(kb + kk) * ldb + bn + nc2 * 8;
            cp16(base + BOFF + off, Bh + gi);
            if (SPLIT3) cp16(base + BOFF + ASZ + off, Bl + gi);
        }
        cp_commit();
    };

    load_stage(0, 0);
    if (NC > 1) load_stage(1, 1);

    const int arow   = wm + (lane & 15);
    const int acol16 = (lane >> 4) * 16;
    const int brow0  = ((lane >> 3) & 1) * 8 + (lane & 7);
    const int bnc    = wn + (lane >> 4) * 8;

    int sidx = 0;
    for (int c = 0; c < NC; c++) {
        if (c + 2 < NC) {
            int ns = sidx + 2; if (ns >= 3) ns -= 3;
            load_stage(ns, c + 2);
            cp_wait2();
        } else if (c + 1 < NC) {
            cp_wait1();
        } else {
            cp_wait0();
        }
        __syncthreads();

        const uint32_t base = sb + (uint32_t)sidx * STG;
#pragma unroll
        for (int ks = 0; ks < 4; ks++) {
            uint32_t ahf[4][4], bhf[8];
#pragma unroll
            for (int mf = 0; mf < 4; mf++) {
                int r = arow + mf * 16;
                uint32_t off = (uint32_t)(r * 128 + ks * 32 + acol16)
                             ^ (uint32_t)((r & 7) << 4);
                ldsm_x4(ahf[mf], base + off);
            }
#pragma unroll
            for (int g2 = 0; g2 < 2; g2++) {
                int kk = ks * 16 + brow0;
                int nn = bnc + g2 * 16;
                uint32_t off = (uint32_t)(kk * 256 + nn * 2)
                             ^ (uint32_t)((kk & 7) << 4);
                ldsm_x4t(&bhf[g2 * 4], base + BOFF + off);
            }
            if (SPLIT3) {
                uint32_t alf[4][4], blf[8];
#pragma unroll
                for (int mf = 0; mf < 4; mf++) {
                    int r = arow + mf * 16;
                    uint32_t off = (uint32_t)(r * 128 + ks * 32 + acol16)
                                 ^ (uint32_t)((r & 7) << 4);
                    ldsm_x4(alf[mf], base + ASZ + off);
                }
#pragma unroll
                for (int g2 = 0; g2 < 2; g2++) {
                    int kk = ks * 16 + brow0;
                    int nn = bnc + g2 * 16;
                    uint32_t off = (uint32_t)(kk * 256 + nn * 2)
                                 ^ (uint32_t)((kk & 7) << 4);
                    ldsm_x4t(&blf[g2 * 4], base + BOFF + ASZ + off);
                }
#pragma unroll
                for (int mf = 0; mf < 4; mf++)
#pragma unroll
                    for (int nf = 0; nf < 4; nf++) {
                        mma_bf16(acc[mf][nf], ahf[mf], bhf[nf * 2], bhf[nf * 2 + 1]);
                        mma_bf16(acc[mf][nf], ahf[mf], blf[nf * 2], blf[nf * 2 + 1]);
                        mma_bf16(acc[mf][nf], alf[mf], bhf[nf * 2], bhf[nf * 2 + 1]);
                    }
            } else {
#pragma unroll
                for (int mf = 0; mf < 4; mf++)
#pragma unroll
                    for (int nf = 0; nf < 4; nf++)
                        mma_fp16(acc[mf][nf], ahf[mf], bhf[nf * 2], bhf[nf * 2 + 1]);
            }
        }
        __syncthreads();
        sidx++; if (sidx == 3) sidx = 0;
    }

    // ---- epilogue ----
    if (RED) {
        // fused reduction: per (row, head) S1, S2, S3 = Σfq, Σfq², Σfq·fk
        float* fk_sm  = (float*)smraw;            // [<=27][128]
        float* red_sm = fk_sm + 27 * 128;         // [2 mg][2 hd][64][3]
        const int q0 = bm / 5;
        const int qn = (bm + 127) / 5 - q0 + 1;   // <= 27
        for (int u = tid; u < qn * 32; u += 256) {
            int r = u >> 5, c4 = u & 31;
            *reinterpret_cast<float4*>(&fk_sm[r * 128 + c4 * 4]) =
                *reinterpret_cast<const float4*>(
                    FK + (size_t)(q0 + r) * INNER + bn + c4 * 4);
        }
        __syncthreads();

        int qi_[8];
        const int wrow_base = (lane >> 2);
#pragma unroll
        for (int ridx = 0; ridx < 8; ridx++) {
            int half = ridx & 1, mf = ridx >> 1;
            int grow = bm + wm + wrow_base + half * 8 + mf * 16;
            qi_[ridx] = grow / 5 - q0;
        }
        float s1[8], s2[8], s3[8];
#pragma unroll
        for (int i = 0; i < 8; i++) { s1[i] = 0.f; s2[i] = 0.f; s3[i] = 0.f; }
#pragma unroll
        for (int mf = 0; mf < 4; mf++)
#pragma unroll
            for (int nf = 0; nf < 4; nf++)
#pragma unroll
                for (int t = 0; t < 4; t++) {
                    int half = t >> 1, j = t & 1;
                    int ridx = mf * 2 + half;
                    float a = acc[mf][nf][t];
                    int col = wn + (lane & 3) * 2 + nf * 8 + j;
                    float kv = fk_sm[qi_[ridx] * 128 + col];
                    s1[ridx] += a;
                    s2[ridx] += a * a;
                    s3[ridx] += a * kv;
                }
#pragma unroll
        for (int r = 0; r < 8; r++)
#pragma unroll
            for (int o = 1; o <= 2; o <<= 1) {
                s1[r] += __shfl_xor_sync(0xffffffffu, s1[r], o);
                s2[r] += __shfl_xor_sync(0xffffffffu, s2[r], o);
                s3[r] += __shfl_xor_sync(0xffffffffu, s3[r], o);
            }
        const int mg = wid >> 2;
        const int hd = (wid & 3) >> 1;
        const bool first = ((wid & 3) & 1) == 0;
        if (first && (lane & 3) == 0) {
#pragma unroll
            for (int r = 0; r < 8; r++) {
                int wrow = (lane >> 2) + (r & 1) * 8 + (r >> 1) * 16;
                float* sl = red_sm + (((mg * 2 + hd) * 64) + wrow) * 3;
                sl[0] = s1[r]; sl[1] = s2[r]; sl[2] = s3[r];
            }
        }
        __syncthreads();
        if (!first && (lane & 3) == 0) {
#pragma unroll
            for (int r = 0; r < 8; r++) {
                int wrow = (lane >> 2) + (r & 1) * 8 + (r >> 1) * 16;
                float* sl = red_sm + (((mg * 2 + hd) * 64) + wrow) * 3;
                int grow = bm + wm + wrow;
                int head = blockIdx.x * 2 + hd;
                float* Rp = Rbuf + ((size_t)grow * HEADS + head) * 3;
                Rp[0] = sl[0] + s1[r];
                Rp[1] = sl[1] + s2[r];
                Rp[2] = sl[2] + s3[r];
            }
        }
        return;
    }

    const int r0 = bm + wm + (lane >> 2);
    const int c0 = bn + wn + (lane & 3) * 2;
    if (OUTH) {
        __half* Ch = (__half*)C_ + (HB ? z * 640 : 0);
#pragma unroll
        for (int mf = 0; mf < 4; mf++)
#pragma unroll
            for (int nf = 0; nf < 4; nf++) {
                int gr0 = r0 + mf * 16;
                int gc  = c0 + nf * 8;
                __half2 v0 = __floats2half2_rn(acc[mf][nf][0], acc[mf][nf][1]);
                __half2 v1 = __floats2half2_rn(acc[mf][nf][2], acc[mf][nf][3]);
                *reinterpret_cast<__half2*>(Ch + (size_t)gr0 * ldc + gc)       = v0;
                *reinterpret_cast<__half2*>(Ch + (size_t)(gr0 + 8) * ldc + gc) = v1;
            }
    } else {
        float* C = (float*)C_;
#pragma unroll
        for (int mf = 0; mf < 4; mf++)
#pragma unroll
            for (int nf = 0; nf < 4; nf++) {
                int gr0 = r0 + mf * 16;
                int gc  = c0 + nf * 8;
                float b0 = 0.f, b1 = 0.f;
                if (BIAS) { b0 = bias[gc]; b1 = bias[gc + 1]; }
                float2 v0 = make_float2(acc[mf][nf][0] + b0, acc[mf][nf][1] + b1);
                float2 v1 = make_float2(acc[mf][nf][2] + b0, acc[mf][nf][3] + b1);
                *reinterpret_cast<float2*>(C + (size_t)gr0 * ldc + gc)       = v0;
                *reinterpret_cast<float2*>(C + (size_t)(gr0 + 8) * ldc + gc) = v1;
            }
    }
}

// ------------------------- fused combine + output assembly ------------------
// Block per q. Warp h: lanes 0..4 compute c[h][n] from reduced sums; then all
// threads build out[q,n,:] = b_out + sum_h c[h][n] * G[q,h,:].
__global__ __launch_bounds__(256) void combine_out_kernel(
    const float* __restrict__ R, const float* __restrict__ kst,
    const __half* __restrict__ G, const float* __restrict__ vs_p,
    const float* __restrict__ cs_p, const float* __restrict__ b_out,
    float* __restrict__ out)
{
    const int q    = blockIdx.x;
    const int tid  = threadIdx.x;
    const int h    = tid >> 5;
    const int lane = tid & 31;
    const float vscale = *vs_p;
    const float cscale = *cs_p;

    __shared__ float c_sm[HEADS][NWAY];
    __shared__ __half G_sm[HEADS * DDIM];

    {
        const float4* Gq = reinterpret_cast<const float4*>(G + (size_t)q * HEADS * DDIM);
        float4* Gs = reinterpret_cast<float4*>(G_sm);
#pragma unroll
        for (int i = tid; i < HEADS * DDIM / 8; i += 256) Gs[i] = Gq[i];
    }

    {
        const int n = (lane < NWAY) ? lane : 0;
        const float* Rp = R + (((size_t)q * NWAY + n) * HEADS + h) * 3;
        const float S1 = Rp[0], S2 = Rp[1], S3 = Rp[2];
        const float* kp = kst + ((size_t)q * HEADS + h) * 3;
        const float mk = kp[0], nk = kp[1], vark = kp[2];

        const float mq   = S1 * (1.f / DH);
        const float varq = S2 * (1.f / DH) - mq * mq;
        const float nq   = sqrtf(S2);
        const float cosd = S3 / (nq * nk);
        const float w    = 1.f / (fabsf(vark - varq) + 1e-6f);
        const float dc   = S3 - mk * S1;
        const float cov  = dc * (1.f / (DH + 1e-6f));
        const float sig  = 1.f / (1.f + expf(-cov));
        const float base = cosd + cscale * sig;

        float vwsum = 0.f;
#pragma unroll
        for (int i = 0; i < NWAY; i++)
            vwsum += __shfl_sync(0xffffffffu, w, i);
        const float inv = 1.f / (vwsum + 1e-6f);
        if (lane < NWAY)
            c_sm[h][lane] = base + vscale * w * inv;
    }
    __syncthreads();

    float* oq = out + (size_t)q * NWAY * DDIM;
    for (int idx = tid; idx < NWAY * DDIM; idx += 256) {
        int n = idx / DDIM, d = idx - n * DDIM;
        float acc = b_out[d];
#pragma unroll
        for (int hh = 0; hh < HEADS; hh++)
            acc += c_sm[hh][n] * __half2float(G_sm[hh * DDIM + d]);
        oq[idx] = acc;
    }
}

// ---------------------------------------------------------------------------
extern "C" void kernel_launch(void* const* d_in, const int* in_sizes, int n_in,
                              void* d_out, int out_size)
{
    const float* q      = (const float*)d_in[0];
    const float* k      = (const float*)d_in[1];
    const float* v      = (const float*)d_in[2];
    const float* ln_g   = (const float*)d_in[3];
    const float* ln_b   = (const float*)d_in[4];
    const float* W_in   = (const float*)d_in[5];
    const float* W_out  = (const float*)d_in[6];
    const float* b_out  = (const float*)d_in[7];
    const float* vscale = (const float*)d_in[8];
    const float* cscale = (const float*)d_in[9];
    float* out = (float*)d_out;

    float *fk, *R, *kst;
    __nv_bfloat16 *qh, *ql, *kh, *kl, *wih, *wil;
    __half *vhf, *fvh, *G, *wif, *wof;
    cudaGetSymbolAddress((void**)&fk,  g_fk);
    cudaGetSymbolAddress((void**)&R,   g_R);
    cudaGetSymbolAddress((void**)&kst, g_kst);
    cudaGetSymbolAddress((void**)&qh,  g_qh);
    cudaGetSymbolAddress((void**)&ql,  g_ql);
    cudaGetSymbolAddress((void**)&kh,  g_kh);
    cudaGetSymbolAddress((void**)&kl,  g_kl);
    cudaGetSymbolAddress((void**)&vhf, g_vhf);
    cudaGetSymbolAddress((void**)&fvh, g_fvh);
    cudaGetSymbolAddress((void**)&G,   g_G);
    cudaGetSymbolAddress((void**)&wih, g_wi_h);
    cudaGetSymbolAddress((void**)&wil, g_wi_l);
    cudaGetSymbolAddress((void**)&wif, g_wi_f);
    cudaGetSymbolAddress((void**)&wof, g_wo_f);

    const int SMEM3 = 3 * 65536 + 128;   // 3-stage split3
    const int SMEM1 = 3 * 32768 + 128;   // 3-stage fp16 single
    const int SMEMG = 32768 + 128;       // 1 chunk (KD=64)
    cudaFuncSetAttribute(
        (const void*)gemm_mma<640, false, true,  false, false, true>,
        cudaFuncAttributeMaxDynamicSharedMemorySize, SMEM3);
    cudaFuncSetAttribute(
        (const void*)gemm_mma<640, false, true,  false, false, false>,
        cudaFuncAttributeMaxDynamicSharedMemorySize, SMEM3);
    cudaFuncSetAttribute(
        (const void*)gemm_mma<640, false, false, true,  false, false>,
        cudaFuncAttributeMaxDynamicSharedMemorySize, SMEM1);
    cudaFuncSetAttribute(
        (const void*)gemm_mma<64,  false, false, true,  true,  false>,
        cudaFuncAttributeMaxDynamicSharedMemorySize, SMEMG);

    // 1) LN: q/k split bf16, v -> fp16
    ln_split_kernel<<<MQ / 8, 256>>>(q, ln_g, ln_b, qh, ql, MQ);
    ln_split_kernel<<<MK / 8, 256>>>(k, ln_g, ln_b, kh, kl, MK);
    ln_half_kernel <<<MK / 8, 256>>>(v, ln_g, ln_b, vhf, MK);

    // 2) weight prep
    wsplit_kernel<<<(DDIM * INNER + 255) / 256, 256>>>(W_in, wih, wil, wif,
                                                       DDIM * INNER);
    whalf_kernel<<<(INNER * DDIM + 255) / 256, 256>>>(W_out, wof, INNER * DDIM);

    // 3) k projection (3-pass bf16) -> fk fp32, then k stats
    gemm_mma<640, false, true, false, false, false>
        <<<dim3(INNER / 128, MK / 128), 256, SMEM3>>>(
            kh, kl, wih, wil, nullptr, fk, nullptr, nullptr,
            DDIM, INNER, INNER);
    kstats_kernel<<<QLEN, 256>>>(fk, kst);

    // 4) q projection (3-pass bf16) with FUSED combine reductions -> R
    gemm_mma<640, false, true, false, false, true>
        <<<dim3(INNER / 128, MQ / 128), 256, SMEM3>>>(
            qh, ql, wih, wil, nullptr, nullptr, fk, R,
            DDIM, INNER, INNER);

    // 5) v projection: single-pass fp16 -> fp16 f_v (linear path)
    gemm_mma<640, false, false, true, false, false>
        <<<dim3(INNER / 128, MK / 128), 256, SMEM1>>>(
            vhf, nullptr, wif, nullptr, nullptr, fvh, nullptr, nullptr,
            DDIM, INNER, INNER);

    // 6) per-head projected V: G[q,h,:] = f_v_head @ W_out_head (fp16, K=64)
    gemm_mma<64, false, false, true, true, false>
        <<<dim3(DDIM / 128, MK / 128, HEADS), 256, SMEMG>>>(
            fvh, nullptr, wof, nullptr, nullptr, G, nullptr, nullptr,
            INNER, DDIM, HEADS * DDIM);

    // 7) fused combine + output assembly
    combine_out_kernel<<<QLEN, 256>>>(R, kst, G, vscale, cscale, b_out, out);
}

// round 8
// speedup vs baseline: 3.8394x; 1.0144x over previous
#include <cuda_runtime.h>
#include <cuda_bf16.h>
#include <cuda_fp16.h>
#include <math.h>
#include <stdint.h>

// ---------------------------------------------------------------------------
// dims fixed for this dataset
#define QLEN   8192
#define NWAY   5
#define DDIM   640
#define INNER  512
#define HEADS  8
#define DH     64
#define MQ     (QLEN * NWAY)   // 40960
#define MK     QLEN            // 8192

// ------------------------- scratch (device globals) ------------------------
__device__ __align__(256) float g_fk[(size_t)MK * INNER];
__device__ __align__(256) float g_R  [(size_t)MQ * HEADS * 3];   // S1,S2,S3
__device__ __align__(256) float g_kst[(size_t)MK * HEADS * 3];   // mk,nk,vark
__device__ __align__(256) __nv_bfloat16 g_qh[(size_t)MQ * DDIM];
__device__ __align__(256) __nv_bfloat16 g_ql[(size_t)MQ * DDIM];
__device__ __align__(256) __nv_bfloat16 g_kh[(size_t)MK * DDIM];
__device__ __align__(256) __nv_bfloat16 g_kl[(size_t)MK * DDIM];
__device__ __align__(256) __half        g_vhf[(size_t)MK * DDIM];    // fp16 LN(v)
__device__ __align__(256) __half        g_fvh[(size_t)MK * INNER];   // fp16 f_v
__device__ __align__(256) __half        g_G  [(size_t)MK * HEADS * DDIM]; // (q,h,d)
__device__ __align__(256) __nv_bfloat16 g_wi_h[(size_t)DDIM * INNER];  // bf16 hi
__device__ __align__(256) __nv_bfloat16 g_wi_l[(size_t)DDIM * INNER];  // bf16 lo
__device__ __align__(256) __half        g_wi_f[(size_t)DDIM * INNER];  // fp16
__device__ __align__(256) __half        g_wo_f[(size_t)INNER * DDIM];  // fp16

// ------------------------- helpers -----------------------------------------
__device__ __forceinline__ uint32_t smem_u32(const void* p) {
    uint32_t a;
    asm("{ .reg .u64 t; cvta.to.shared.u64 t, %1; cvt.u32.u64 %0, t; }"
        : "=r"(a) : "l"(p));
    return a;
}
__device__ __forceinline__ void cp16(uint32_t dst, const void* src) {
    asm volatile(
        "{ .reg .u64 g; cvta.to.global.u64 g, %1;"
        " cp.async.cg.shared.global [%0], [g], 16; }"
        :: "r"(dst), "l"(src) : "memory");
}
__device__ __forceinline__ void cp_commit() {
    asm volatile("cp.async.commit_group;" ::: "memory");
}
__device__ __forceinline__ void cp_wait0() {
    asm volatile("cp.async.wait_group 0;" ::: "memory");
}
__device__ __forceinline__ void cp_wait1() {
    asm volatile("cp.async.wait_group 1;" ::: "memory");
}
__device__ __forceinline__ void cp_wait2() {
    asm volatile("cp.async.wait_group 2;" ::: "memory");
}
__device__ __forceinline__ void ldsm_x4(uint32_t* r, uint32_t addr) {
    asm volatile("ldmatrix.sync.aligned.m8n8.x4.shared.b16 {%0,%1,%2,%3}, [%4];"
                 : "=r"(r[0]), "=r"(r[1]), "=r"(r[2]), "=r"(r[3]) : "r"(addr));
}
__device__ __forceinline__ void ldsm_x4t(uint32_t* r, uint32_t addr) {
    asm volatile("ldmatrix.sync.aligned.m8n8.x4.trans.shared.b16 {%0,%1,%2,%3}, [%4];"
                 : "=r"(r[0]), "=r"(r[1]), "=r"(r[2]), "=r"(r[3]) : "r"(addr));
}
__device__ __forceinline__ void mma_bf16(float* c, const uint32_t* a,
                                         uint32_t b0, uint32_t b1) {
    asm volatile(
        "mma.sync.aligned.m16n8k16.row.col.f32.bf16.bf16.f32 "
        "{%0,%1,%2,%3}, {%4,%5,%6,%7}, {%8,%9}, {%0,%1,%2,%3};"
        : "+f"(c[0]), "+f"(c[1]), "+f"(c[2]), "+f"(c[3])
        : "r"(a[0]), "r"(a[1]), "r"(a[2]), "r"(a[3]), "r"(b0), "r"(b1));
}
__device__ __forceinline__ void mma_fp16(float* c, const uint32_t* a,
                                         uint32_t b0, uint32_t b1) {
    asm volatile(
        "mma.sync.aligned.m16n8k16.row.col.f32.f16.f16.f32 "
        "{%0,%1,%2,%3}, {%4,%5,%6,%7}, {%8,%9}, {%0,%1,%2,%3};"
        : "+f"(c[0]), "+f"(c[1]), "+f"(c[2]), "+f"(c[3])
        : "r"(a[0]), "r"(a[1]), "r"(a[2]), "r"(a[3]), "r"(b0), "r"(b1));
}

// ------------------------- fused LN for q, k, v -----------------------------
// rows [0,MQ): q -> bf16 split; [MQ,MQ+MK): k -> bf16 split; rest: v -> fp16
__global__ __launch_bounds__(256) void ln_all_kernel(
    const float* __restrict__ Q, const float* __restrict__ K,
    const float* __restrict__ V, const float* __restrict__ g,
    const float* __restrict__ b,
    __nv_bfloat16* __restrict__ qh, __nv_bfloat16* __restrict__ ql,
    __nv_bfloat16* __restrict__ kh, __nv_bfloat16* __restrict__ kl,
    __half* __restrict__ vhf)
{
    int row  = blockIdx.x * 8 + (threadIdx.x >> 5);
    int lane = threadIdx.x & 31;
    const float* x;
    int seg, lrow;
    if (row < MQ)            { seg = 0; lrow = row;          x = Q + (size_t)lrow * DDIM; }
    else if (row < MQ + MK)  { seg = 1; lrow = row - MQ;     x = K + (size_t)lrow * DDIM; }
    else                     { seg = 2; lrow = row - MQ - MK; x = V + (size_t)lrow * DDIM; }

    float v[20];
    float s = 0.f, s2 = 0.f;
#pragma unroll
    for (int i = 0; i < 20; i++) {
        v[i] = x[lane + i * 32];
        s += v[i]; s2 += v[i] * v[i];
    }
#pragma unroll
    for (int o = 16; o > 0; o >>= 1) {
        s  += __shfl_xor_sync(0xffffffffu, s,  o);
        s2 += __shfl_xor_sync(0xffffffffu, s2, o);
    }
    float m   = s * (1.f / DDIM);
    float var = s2 * (1.f / DDIM) - m * m;
    float rs  = rsqrtf(var + 1e-5f);
#pragma unroll
    for (int i = 0; i < 20; i++) {
        int c = lane + i * 32;
        float xn = (v[i] - m) * rs * g[c] + b[c];
        size_t o0 = (size_t)lrow * DDIM + c;
        if (seg == 0) {
            __nv_bfloat16 h = __float2bfloat16(xn);
            qh[o0] = h;
            ql[o0] = __float2bfloat16(xn - __bfloat162float(h));
        } else if (seg == 1) {
            __nv_bfloat16 h = __float2bfloat16(xn);
            kh[o0] = h;
            kl[o0] = __float2bfloat16(xn - __bfloat162float(h));
        } else {
            vhf[o0] = __float2half(xn);
        }
    }
}

// ------------------------- fused W prep -------------------------------------
__global__ __launch_bounds__(256) void wprep_all_kernel(
    const float* __restrict__ Win, const float* __restrict__ Wout,
    __nv_bfloat16* __restrict__ Th, __nv_bfloat16* __restrict__ Tl,
    __half* __restrict__ Tf, __half* __restrict__ Tof)
{
    int idx = blockIdx.x * 256 + threadIdx.x;
    const int TOT = DDIM * INNER;
    if (idx < TOT) {
        float w = Win[idx];
        __nv_bfloat16 h = __float2bfloat16(w);
        Th[idx] = h;
        Tl[idx] = __float2bfloat16(w - __bfloat162float(h));
        Tf[idx] = __float2half(w);
    } else if (idx < 2 * TOT) {
        Tof[idx - TOT] = __float2half(Wout[idx - TOT]);
    }
}

// ------------------------- GEMM body ----------------------------------------
// MODE 0: 1-pass fp16. MODE 1: 3-pass bf16 split (drops AlBl).
// EPI 0: plain C write (fp32 or fp16 via OUTH).
// EPI 1: no C write; reduce S1=Σfq, S2=Σfq², S3=Σfq·fk per (row, head) -> Rbuf.
// EPI 2: C write (fp32) + k-stats (mk, nk, vark) per (row, head) -> Rbuf.
template <int KD, int MODE, bool OUTH, bool BIAS, int EPI>
__device__ __forceinline__ void gemm_body(
    int bm, int bn,
    const uint16_t* __restrict__ Ah, const uint16_t* __restrict__ Al,
    const uint16_t* __restrict__ Bh, const uint16_t* __restrict__ Bl,
    const float* __restrict__ bias, void* __restrict__ C_,
    const float* __restrict__ FK, float* __restrict__ Rbuf,
    int lda, int ldb, int ldc, char* smraw)
{
    constexpr int NC    = KD / 64;
    constexpr int STG   = (MODE == 1) ? 65536 : 32768;
    constexpr int BOFF  = (MODE == 1) ? 32768 : 16384;
    constexpr int BLOFF = 49152;

    const uint32_t sb = (smem_u32(smraw) + 127u) & ~127u;

    const int tid  = threadIdx.x;
    const int lane = tid & 31;
    const int wid  = tid >> 5;
    const int wm   = (wid >> 2) * 64;
    const int wn   = (wid & 3) * 32;

    float acc[4][4][4];
#pragma unroll
    for (int i = 0; i < 4; i++)
#pragma unroll
        for (int j = 0; j < 4; j++)
#pragma unroll
            for (int t = 0; t < 4; t++) acc[i][j][t] = 0.f;

    auto load_stage = [&](int s, int c) {
        const uint32_t base = sb + (uint32_t)s * STG;
        const int kb = c * 64;
#pragma unroll
        for (int u = tid; u < 1024; u += 256) {
            int r = u >> 3, kc = u & 7;
            uint32_t off = (uint32_t)(r * 128 + kc * 16) ^ (uint32_t)((r & 7) << 4);
            const size_t gi = (size_t)(bm + r) * lda + kb + kc * 8;
            cp16(base + off, Ah + gi);
            if (MODE == 1) cp16(base + 16384 + off, Al + gi);
        }
#pragma unroll
        for (int u = tid; u < 1024; u += 256) {
            int kk = u >> 4, nc2 = u & 15;
            uint32_t off = (uint32_t)(kk * 256 + nc2 * 16) ^ (uint32_t)((kk & 7) << 4);
            const size_t gi = (size_t)(kb + kk) * ldb + bn + nc2 * 8;
            cp16(base + BOFF + off, Bh + gi);
            if (MODE == 1) cp16(base + BLOFF + off, Bl + gi);
        }
        cp_commit();
    };

    load_stage(0, 0);
    if (NC > 1) load_stage(1, 1);

    const int arow   = wm + (lane & 15);
    const int acol16 = (lane >> 4) * 16;
    const int brow0  = ((lane >> 3) & 1) * 8 + (lane & 7);
    const int bnc    = wn + (lane >> 4) * 8;

    int sidx = 0;
    for (int c = 0; c < NC; c++) {
        if (c + 2 < NC) {
            int ns = sidx + 2; if (ns >= 3) ns -= 3;
            load_stage(ns, c + 2);
            cp_wait2();
        } else if (c + 1 < NC) {
            cp_wait1();
        } else {
            cp_wait0();
        }
        __syncthreads();

        const uint32_t base = sb + (uint32_t)sidx * STG;
#pragma unroll
        for (int ks = 0; ks < 4; ks++) {
            uint32_t ahf[4][4], bhf[8];
#pragma unroll
            for (int mf = 0; mf < 4; mf++) {
                int r = arow + mf * 16;
                uint32_t off = (uint32_t)(r * 128 + ks * 32 + acol16)
                             ^ (uint32_t)((r & 7) << 4);
                ldsm_x4(ahf[mf], base + off);
            }
#pragma unroll
            for (int g2 = 0; g2 < 2; g2++) {
                int kk = ks * 16 + brow0;
                int nn = bnc + g2 * 16;
                uint32_t off = (uint32_t)(kk * 256 + nn * 2)
                             ^ (uint32_t)((kk & 7) << 4);
                ldsm_x4t(&bhf[g2 * 4], base + BOFF + off);
            }
            if (MODE == 1) {
                uint32_t alf[4][4], blf[8];
#pragma unroll
                for (int mf = 0; mf < 4; mf++) {
                    int r = arow + mf * 16;
                    uint32_t off = (uint32_t)(r * 128 + ks * 32 + acol16)
                                 ^ (uint32_t)((r & 7) << 4);
                    ldsm_x4(alf[mf], base + 16384 + off);
                }
#pragma unroll
                for (int g2 = 0; g2 < 2; g2++) {
                    int kk = ks * 16 + brow0;
                    int nn = bnc + g2 * 16;
                    uint32_t off = (uint32_t)(kk * 256 + nn * 2)
                                 ^ (uint32_t)((kk & 7) << 4);
                    ldsm_x4t(&blf[g2 * 4], base + BLOFF + off);
                }
#pragma unroll
                for (int mf = 0; mf < 4; mf++)
#pragma unroll
                    for (int nf = 0; nf < 4; nf++) {
                        mma_bf16(acc[mf][nf], ahf[mf], bhf[nf * 2], bhf[nf * 2 + 1]);
                        mma_bf16(acc[mf][nf], ahf[mf], blf[nf * 2], blf[nf * 2 + 1]);
                        mma_bf16(acc[mf][nf], alf[mf], bhf[nf * 2], bhf[nf * 2 + 1]);
                    }
            } else {
#pragma unroll
                for (int mf = 0; mf < 4; mf++)
#pragma unroll
                    for (int nf = 0; nf < 4; nf++)
                        mma_fp16(acc[mf][nf], ahf[mf], bhf[nf * 2], bhf[nf * 2 + 1]);
            }
        }
        __syncthreads();
        sidx++; if (sidx == 3) sidx = 0;
    }

    const int mg = wid >> 2;
    const int hd = (wid & 3) >> 1;
    const bool first = ((wid & 3) & 1) == 0;

    // ---- EPI 1: q-path fused reductions (no C write) ----
    if (EPI == 1) {
        float* fk_sm  = (float*)smraw;            // [<=27][128]
        float* red_sm = fk_sm + 27 * 128;         // [2][2][64][3]
        const int q0 = bm / 5;
        const int qn = (bm + 127) / 5 - q0 + 1;   // <= 27
        for (int u = tid; u < qn * 32; u += 256) {
            int r = u >> 5, c4 = u & 31;
            *reinterpret_cast<float4*>(&fk_sm[r * 128 + c4 * 4]) =
                *reinterpret_cast<const float4*>(
                    FK + (size_t)(q0 + r) * INNER + bn + c4 * 4);
        }
        __syncthreads();

        int qi_[8];
        const int wrow_base = (lane >> 2);
#pragma unroll
        for (int ridx = 0; ridx < 8; ridx++) {
            int half = ridx & 1, mf = ridx >> 1;
            int grow = bm + wm + wrow_base + half * 8 + mf * 16;
            qi_[ridx] = grow / 5 - q0;
        }
        float s1[8], s2[8], s3[8];
#pragma unroll
        for (int i = 0; i < 8; i++) { s1[i] = 0.f; s2[i] = 0.f; s3[i] = 0.f; }
#pragma unroll
        for (int mf = 0; mf < 4; mf++)
#pragma unroll
            for (int nf = 0; nf < 4; nf++)
#pragma unroll
                for (int t = 0; t < 4; t++) {
                    int half = t >> 1, j = t & 1;
                    int ridx = mf * 2 + half;
                    float a = acc[mf][nf][t];
                    int col = wn + (lane & 3) * 2 + nf * 8 + j;
                    float kv = fk_sm[qi_[ridx] * 128 + col];
                    s1[ridx] += a;
                    s2[ridx] += a * a;
                    s3[ridx] += a * kv;
                }
#pragma unroll
        for (int r = 0; r < 8; r++)
#pragma unroll
            for (int o = 1; o <= 2; o <<= 1) {
                s1[r] += __shfl_xor_sync(0xffffffffu, s1[r], o);
                s2[r] += __shfl_xor_sync(0xffffffffu, s2[r], o);
                s3[r] += __shfl_xor_sync(0xffffffffu, s3[r], o);
            }
        if (first && (lane & 3) == 0) {
#pragma unroll
            for (int r = 0; r < 8; r++) {
                int wrow = (lane >> 2) + (r & 1) * 8 + (r >> 1) * 16;
                float* sl = red_sm + (((mg * 2 + hd) * 64) + wrow) * 3;
                sl[0] = s1[r]; sl[1] = s2[r]; sl[2] = s3[r];
            }
        }
        __syncthreads();
        if (!first && (lane & 3) == 0) {
#pragma unroll
            for (int r = 0; r < 8; r++) {
                int wrow = (lane >> 2) + (r & 1) * 8 + (r >> 1) * 16;
                float* sl = red_sm + (((mg * 2 + hd) * 64) + wrow) * 3;
                int grow = bm + wm + wrow;
                int head = (bn >> 6) + hd;
                float* Rp = Rbuf + ((size_t)grow * HEADS + head) * 3;
                Rp[0] = sl[0] + s1[r];
                Rp[1] = sl[1] + s2[r];
                Rp[2] = sl[2] + s3[r];
            }
        }
        return;
    }

    // ---- normal C write ----
    const int r0 = bm + wm + (lane >> 2);
    const int c0 = bn + wn + (lane & 3) * 2;
    if (OUTH) {
        __half* Ch = (__half*)C_;
#pragma unroll
        for (int mf = 0; mf < 4; mf++)
#pragma unroll
            for (int nf = 0; nf < 4; nf++) {
                int gr0 = r0 + mf * 16;
                int gc  = c0 + nf * 8;
                __half2 v0 = __floats2half2_rn(acc[mf][nf][0], acc[mf][nf][1]);
                __half2 v1 = __floats2half2_rn(acc[mf][nf][2], acc[mf][nf][3]);
                *reinterpret_cast<__half2*>(Ch + (size_t)gr0 * ldc + gc)       = v0;
                *reinterpret_cast<__half2*>(Ch + (size_t)(gr0 + 8) * ldc + gc) = v1;
            }
    } else {
        float* C = (float*)C_;
#pragma unroll
        for (int mf = 0; mf < 4; mf++)
#pragma unroll
            for (int nf = 0; nf < 4; nf++) {
                int gr0 = r0 + mf * 16;
                int gc  = c0 + nf * 8;
                float b0 = 0.f, b1 = 0.f;
                if (BIAS) { b0 = bias[gc]; b1 = bias[gc + 1]; }
                float2 v0 = make_float2(acc[mf][nf][0] + b0, acc[mf][nf][1] + b1);
                float2 v1 = make_float2(acc[mf][nf][2] + b0, acc[mf][nf][3] + b1);
                *reinterpret_cast<float2*>(C + (size_t)gr0 * ldc + gc)       = v0;
                *reinterpret_cast<float2*>(C + (size_t)(gr0 + 8) * ldc + gc) = v1;
            }
    }

    // ---- EPI 2: fused k stats (mk, nk, vark) ----
    if (EPI == 2) {
        float s1[8], s2[8];
#pragma unroll
        for (int i = 0; i < 8; i++) { s1[i] = 0.f; s2[i] = 0.f; }
#pragma unroll
        for (int mf = 0; mf < 4; mf++)
#pragma unroll
            for (int nf = 0; nf < 4; nf++)
#pragma unroll
                for (int t = 0; t < 4; t++) {
                    int ridx = mf * 2 + (t >> 1);
                    float a = acc[mf][nf][t];
                    s1[ridx] += a;
                    s2[ridx] += a * a;
                }
#pragma unroll
        for (int r = 0; r < 8; r++)
#pragma unroll
            for (int o = 1; o <= 2; o <<= 1) {
                s1[r] += __shfl_xor_sync(0xffffffffu, s1[r], o);
                s2[r] += __shfl_xor_sync(0xffffffffu, s2[r], o);
            }
        float* red_sm = (float*)smraw;   // [2][2][64][2]
        if (first && (lane & 3) == 0) {
#pragma unroll
            for (int r = 0; r < 8; r++) {
                int wrow = (lane >> 2) + (r & 1) * 8 + (r >> 1) * 16;
                float* sl = red_sm + (((mg * 2 + hd) * 64) + wrow) * 2;
                sl[0] = s1[r]; sl[1] = s2[r];
            }
        }
        __syncthreads();
        if (!first && (lane & 3) == 0) {
#pragma unroll
            for (int r = 0; r < 8; r++) {
                int wrow = (lane >> 2) + (r & 1) * 8 + (r >> 1) * 16;
                float* sl = red_sm + (((mg * 2 + hd) * 64) + wrow) * 2;
                int grow = bm + wm + wrow;
                int head = (bn >> 6) + hd;
                float S1 = sl[0] + s1[r];
                float S2 = sl[1] + s2[r];
                float mk = S1 * (1.f / DH);
                float* Kp = Rbuf + ((size_t)grow * HEADS + head) * 3;
                Kp[0] = mk;
                Kp[1] = sqrtf(S2);
                Kp[2] = S2 * (1.f / DH) - mk * mk;
            }
        }
    }
}

// ------------------------- merged GEMM launches ------------------------------
// launch A: z=0 -> k-projection (3-pass bf16 + fused k-stats);
//           z=1 -> v-projection (1-pass fp16 -> fp16 f_v)
__global__ __launch_bounds__(256, 1) void kv_gemm_kernel(
    const __nv_bfloat16* __restrict__ kh, const __nv_bfloat16* __restrict__ kl,
    const __nv_bfloat16* __restrict__ wih, const __nv_bfloat16* __restrict__ wil,
    float* __restrict__ fk, float* __restrict__ kst,
    const __half* __restrict__ vhf, const __half* __restrict__ wif,
    __half* __restrict__ fvh)
{
    extern __shared__ char sm[];
    const int bm = blockIdx.y * 128;
    const int bn = blockIdx.x * 128;
    if (blockIdx.z == 0)
        gemm_body<640, 1, false, false, 2>(
            bm, bn, (const uint16_t*)kh, (const uint16_t*)kl,
            (const uint16_t*)wih, (const uint16_t*)wil,
            nullptr, fk, nullptr, kst, DDIM, INNER, INNER, sm);
    else
        gemm_body<640, 0, true, false, 0>(
            bm, bn, (const uint16_t*)vhf, nullptr,
            (const uint16_t*)wif, nullptr,
            nullptr, fvh, nullptr, nullptr, DDIM, INNER, INNER, sm);
}

// launch B: ids [0,1280) -> q-projection (3-pass bf16 + fused reductions);
//           ids [1280,3840) -> per-head projected V (fp16, K=64)
__global__ __launch_bounds__(256, 1) void qg_gemm_kernel(
    const __nv_bfloat16* __restrict__ qh, const __nv_bfloat16* __restrict__ ql,
    const __nv_bfloat16* __restrict__ wih, const __nv_bfloat16* __restrict__ wil,
    const float* __restrict__ fk, float* __restrict__ R,
    const __half* __restrict__ fvh, const __half* __restrict__ wof,
    __half* __restrict__ G)
{
    extern __shared__ char sm[];
    const int id = blockIdx.x;
    if (id < 1280) {
        const int bm = (id >> 2) * 128;
        const int bn = (id & 3) * 128;
        gemm_body<640, 1, false, false, 1>(
            bm, bn, (const uint16_t*)qh, (const uint16_t*)ql,
            (const uint16_t*)wih, (const uint16_t*)wil,
            nullptr, nullptr, fk, R, DDIM, INNER, INNER, sm);
    } else {
        const int gid = id - 1280;
        const int z   = gid / 320;          // head
        const int rem = gid - z * 320;
        const int bm  = (rem / 5) * 128;
        const int bn  = (rem % 5) * 128;
        gemm_body<64, 0, true, false, 0>(
            bm, bn, (const uint16_t*)fvh + z * 64, nullptr,
            (const uint16_t*)wof + (size_t)z * 64 * DDIM, nullptr,
            nullptr, (__half*)G + z * DDIM, nullptr, nullptr,
            INNER, DDIM, HEADS * DDIM, sm);
    }
}

// ------------------------- fused combine + output assembly ------------------
__global__ __launch_bounds__(256) void combine_out_kernel(
    const float* __restrict__ R, const float* __restrict__ kst,
    const __half* __restrict__ G, const float* __restrict__ vs_p,
    const float* __restrict__ cs_p, const float* __restrict__ b_out,
    float* __restrict__ out)
{
    const int q    = blockIdx.x;
    const int tid  = threadIdx.x;
    const int h    = tid >> 5;
    const int lane = tid & 31;
    const float vscale = *vs_p;
    const float cscale = *cs_p;

    __shared__ float c_sm[HEADS][NWAY];
    __shared__ __half G_sm[HEADS * DDIM];

    {
        const float4* Gq = reinterpret_cast<const float4*>(G + (size_t)q * HEADS * DDIM);
        float4* Gs = reinterpret_cast<float4*>(G_sm);
#pragma unroll
        for (int i = tid; i < HEADS * DDIM / 8; i += 256) Gs[i] = Gq[i];
    }

    {
        const int n = (lane < NWAY) ? lane : 0;
        const float* Rp = R + (((size_t)q * NWAY + n) * HEADS + h) * 3;
        const float S1 = Rp[0], S2 = Rp[1], S3 = Rp[2];
        const float* kp = kst + ((size_t)q * HEADS + h) * 3;
        const float mk = kp[0], nk = kp[1], vark = kp[2];

        const float mq   = S1 * (1.f / DH);
        const float varq = S2 * (1.f / DH) - mq * mq;
        const float nq   = sqrtf(S2);
        const float cosd = S3 / (nq * nk);
        const float w    = 1.f / (fabsf(vark - varq) + 1e-6f);
        const float dc   = S3 - mk * S1;
        const float cov  = dc * (1.f / (DH + 1e-6f));
        const float sig  = 1.f / (1.f + expf(-cov));
        const float base = cosd + cscale * sig;

        float vwsum = 0.f;
#pragma unroll
        for (int i = 0; i < NWAY; i++)
            vwsum += __shfl_sync(0xffffffffu, w, i);
        const float inv = 1.f / (vwsum + 1e-6f);
        if (lane < NWAY)
            c_sm[h][lane] = base + vscale * w * inv;
    }
    __syncthreads();

    float* oq = out + (size_t)q * NWAY * DDIM;
    for (int idx = tid; idx < NWAY * DDIM; idx += 256) {
        int n = idx / DDIM, d = idx - n * DDIM;
        float acc = b_out[d];
#pragma unroll
        for (int hh = 0; hh < HEADS; hh++)
            acc += c_sm[hh][n] * __half2float(G_sm[hh * DDIM + d]);
        oq[idx] = acc;
    }
}

// ---------------------------------------------------------------------------
extern "C" void kernel_launch(void* const* d_in, const int* in_sizes, int n_in,
                              void* d_out, int out_size)
{
    const float* q      = (const float*)d_in[0];
    const float* k      = (const float*)d_in[1];
    const float* v      = (const float*)d_in[2];
    const float* ln_g   = (const float*)d_in[3];
    const float* ln_b   = (const float*)d_in[4];
    const float* W_in   = (const float*)d_in[5];
    const float* W_out  = (const float*)d_in[6];
    const float* b_out  = (const float*)d_in[7];
    const float* vscale = (const float*)d_in[8];
    const float* cscale = (const float*)d_in[9];
    float* out = (float*)d_out;

    float *fk, *R, *kst;
    __nv_bfloat16 *qh, *ql, *kh, *kl, *wih, *wil;
    __half *vhf, *fvh, *G, *wif, *wof;
    cudaGetSymbolAddress((void**)&fk,  g_fk);
    cudaGetSymbolAddress((void**)&R,   g_R);
    cudaGetSymbolAddress((void**)&kst, g_kst);
    cudaGetSymbolAddress((void**)&qh,  g_qh);
    cudaGetSymbolAddress((void**)&ql,  g_ql);
    cudaGetSymbolAddress((void**)&kh,  g_kh);
    cudaGetSymbolAddress((void**)&kl,  g_kl);
    cudaGetSymbolAddress((void**)&vhf, g_vhf);
    cudaGetSymbolAddress((void**)&fvh, g_fvh);
    cudaGetSymbolAddress((void**)&G,   g_G);
    cudaGetSymbolAddress((void**)&wih, g_wi_h);
    cudaGetSymbolAddress((void**)&wil, g_wi_l);
    cudaGetSymbolAddress((void**)&wif, g_wi_f);
    cudaGetSymbolAddress((void**)&wof, g_wo_f);

    const int SMEM = 3 * 65536 + 128;   // 196736
    cudaFuncSetAttribute((const void*)kv_gemm_kernel,
                         cudaFuncAttributeMaxDynamicSharedMemorySize, SMEM);
    cudaFuncSetAttribute((const void*)qg_gemm_kernel,
                         cudaFuncAttributeMaxDynamicSharedMemorySize, SMEM);

    // 1) fused LN (q bf16-split, k bf16-split, v fp16)
    ln_all_kernel<<<(MQ + 2 * MK) / 8, 256>>>(
        q, k, v, ln_g, ln_b, qh, ql, kh, kl, vhf);

    // 2) fused weight prep
    wprep_all_kernel<<<(2 * DDIM * INNER + 255) / 256, 256>>>(
        W_in, W_out, wih, wil, wif, wof);

    // 3) k-projection (+ fused k-stats) and v-projection in one launch
    kv_gemm_kernel<<<dim3(4, 64, 2), 256, SMEM>>>(
        kh, kl, wih, wil, fk, kst, vhf, wif, fvh);

    // 4) q-projection (+ fused combine reductions) and per-head G in one launch
    qg_gemm_kernel<<<3840, 256, SMEM>>>(
        qh, ql, wih, wil, fk, R, fvh, wof, G);

    // 5) fused combine + output assembly
    combine_out_kernel<<<QLEN, 256>>>(R, kst, G, vscale, cscale, b_out, out);
}